// round 4
// baseline (speedup 1.0000x reference)
#include <cuda_runtime.h>

#define T_SIM 100
#define NB 32
// e^{-1/tau}, tau = 10
#define R_DEC 0.9048374180359595f
// e/tau
#define C_EPS 0.2718281828459045f

// ---------------- scratch (device globals; no allocation allowed) -------------
__device__ float g_S0 [T_SIM * NB * 784];          // spikes in   [t][b][28][28]
__device__ float g_U1 [T_SIM * NB * 16 * 784];     // conv1 raw membrane input
__device__ float g_S1p[T_SIM * NB * 16 * 196];     // fused psp+spike+pool+psp+spike
__device__ float g_U2 [T_SIM * NB * 32 * 196];     // conv2 raw membrane input
__device__ float g_S2p[T_SIM * NB * 1568];         // fused chain out (A matrix of fc1)
__device__ float g_U3 [T_SIM * NB * 410];          // fc1 out -> spikes (in place)
__device__ float g_U4 [T_SIM * NB * 10];           // fc2 out (psp+spike fused in final)
__device__ float g_W1R[400];                        // w1 reordered [kq][oc]
__device__ float g_W2R[12800];                      // w2 reordered [ci*25+kq][oc]

// ---------------- encode: bernoulli spikes + transpose to time-major ----------
__global__ void k_encode(const float* __restrict__ rand_u, const float* __restrict__ img) {
    int i = blockIdx.x * blockDim.x + threadIdx.x;
    if (i >= T_SIM * NB * 784) return;
    int bp = i / T_SIM;                 // (b,y,x) flat
    int t  = i - bp * T_SIM;
    float s = (rand_u[i] < img[bp]) ? 1.0f : 0.0f;
    g_S0[t * (NB * 784) + bp] = s;
}

// ---------------- weight reorder (oc innermost for vector loads) --------------
__global__ void k_reorder(const float* __restrict__ w1, const float* __restrict__ w2) {
    int i = blockIdx.x * blockDim.x + threadIdx.x;
    if (i < 400) {
        int oc = i & 15, kq = i >> 4;
        g_W1R[i] = w1[oc * 25 + kq];
    }
    if (i < 12800) {
        int oc = i & 31, kk = i >> 5;
        int ci = kk / 25, kq = kk % 25;
        g_W2R[i] = w2[(oc * 16 + ci) * 25 + kq];
    }
}

// ---------------- conv1: 1->16ch, 28x28, 5x5 pad2, per (t,b) plane -------------
__global__ void k_conv1() {
    __shared__ float in_s[32 * 32];   // padded 28+4
    __shared__ float w_s[400];
    int tb = blockIdx.x; int t = tb >> 5, b = tb & 31;
    int tid = threadIdx.x;            // 448 threads
    for (int i = tid; i < 1024; i += blockDim.x) in_s[i] = 0.f;
    __syncthreads();
    const float* src = &g_S0[t * (NB * 784) + b * 784];
    for (int i = tid; i < 784; i += blockDim.x) {
        int y = i / 28, x = i - y * 28;
        in_s[(y + 2) * 32 + (x + 2)] = src[i];
    }
    for (int i = tid; i < 400; i += blockDim.x) w_s[i] = g_W1R[i];
    __syncthreads();

    int ocg = tid / 112; int rem = tid % 112;
    int y = rem >> 2; int x0 = (rem & 3) * 7;
    float acc[4][7];
    #pragma unroll
    for (int o = 0; o < 4; o++)
        #pragma unroll
        for (int xx = 0; xx < 7; xx++) acc[o][xx] = 0.f;

    #pragma unroll
    for (int ky = 0; ky < 5; ky++) {
        float rin[11];
        #pragma unroll
        for (int j = 0; j < 11; j++) rin[j] = in_s[(y + ky) * 32 + x0 + j];
        #pragma unroll
        for (int kx = 0; kx < 5; kx++) {
            float4 w = *(const float4*)&w_s[(ky * 5 + kx) * 16 + ocg * 4];
            #pragma unroll
            for (int xx = 0; xx < 7; xx++) {
                float v = rin[kx + xx];
                acc[0][xx] += w.x * v; acc[1][xx] += w.y * v;
                acc[2][xx] += w.z * v; acc[3][xx] += w.w * v;
            }
        }
    }
    float* dst = &g_U1[t * (NB * 12544) + b * 12544];
    #pragma unroll
    for (int o = 0; o < 4; o++)
        #pragma unroll
        for (int xx = 0; xx < 7; xx++)
            dst[(ocg * 4 + o) * 784 + y * 28 + x0 + xx] = acc[o][xx];
}

// ------- fused: psp+spike (full res) -> 2x2 pool(x1.1) -> psp+spike ------------
// One thread per POOLED output pixel. 4 input PSP states + 1 output PSP state
// live in registers; the full-res spike tensor never touches memory.
__global__ void k_fused_pp(const float* __restrict__ uin, float* __restrict__ sout,
                           int Hin, int planeIn, int planeOut, int total) {
    int i = blockIdx.x * blockDim.x + threadIdx.x;
    if (i >= total) return;
    int ho = Hin >> 1;
    int x  = i % ho;
    int y  = (i / ho) % ho;
    int bc = i / (ho * ho);
    const float* base = uin + bc * Hin * Hin + (2 * y) * Hin + 2 * x;

    float a1 = 0.f, a2 = 0.f;   // stream (0,0)
    float b1 = 0.f, b2 = 0.f;   // stream (0,1)
    float c1 = 0.f, c2 = 0.f;   // stream (1,0)
    float d1 = 0.f, d2 = 0.f;   // stream (1,1)
    float o1 = 0.f, o2 = 0.f;   // output psp state

    #pragma unroll 4
    for (int t = 0; t < T_SIM; t++) {
        float2 top = *(const float2*)(base + (size_t)t * planeIn);
        float2 bot = *(const float2*)(base + (size_t)t * planeIn + Hin);

        a2 = R_DEC * (a2 + a1); a1 = R_DEC * a1 + top.x;
        b2 = R_DEC * (b2 + b1); b1 = R_DEC * b1 + top.y;
        c2 = R_DEC * (c2 + c1); c1 = R_DEC * c1 + bot.x;
        d2 = R_DEC * (d2 + d1); d1 = R_DEC * d1 + bot.y;

        float spkA = (C_EPS * a2 >= 1.0f) ? 1.0f : 0.0f;
        float spkB = (C_EPS * b2 >= 1.0f) ? 1.0f : 0.0f;
        float spkC = (C_EPS * c2 >= 1.0f) ? 1.0f : 0.0f;
        float spkD = (C_EPS * d2 >= 1.0f) ? 1.0f : 0.0f;
        float pool = 1.1f * ((spkA + spkB) + (spkC + spkD));

        o2 = R_DEC * (o2 + o1); o1 = R_DEC * o1 + pool;
        sout[(size_t)t * planeOut + i] = (C_EPS * o2 >= 1.0f) ? 1.0f : 0.0f;
    }
}

// ---------------- generic psp + spike (in place, scan over t) ------------------
__global__ void k_psp(float* __restrict__ u, int plane) {
    int i = blockIdx.x * blockDim.x + threadIdx.x;
    if (i >= plane) return;
    float* p = u + i;
    float s1 = 0.f, s2 = 0.f;
    #pragma unroll 4
    for (int t = 0; t < T_SIM; t++) {
        float x = p[(size_t)t * plane];
        s2 = R_DEC * (s2 + s1);        // y[t] uses state at t-1  (eps[0] = 0)
        s1 = R_DEC * s1 + x;
        p[(size_t)t * plane] = (C_EPS * s2 >= 1.0f) ? 1.0f : 0.0f;
    }
}

// ---------------- conv2: 16->32ch, 14x14, 5x5 pad2, per (t,b) plane ------------
__global__ void k_conv2() {
    __shared__ float in_s[16 * 18 * 18];   // 5184 floats, padded 14+4
    int tb = blockIdx.x; int t = tb >> 5, b = tb & 31;
    int tid = threadIdx.x;                 // 224 threads
    for (int i = tid; i < 5184; i += blockDim.x) in_s[i] = 0.f;
    __syncthreads();
    const float* src = &g_S1p[t * (NB * 3136) + b * 3136];
    for (int i = tid; i < 3136; i += blockDim.x) {
        int ci = i / 196, r = i - ci * 196;
        int y = r / 14, x = r - y * 14;
        in_s[ci * 324 + (y + 2) * 18 + (x + 2)] = src[i];
    }
    __syncthreads();

    int ocg = tid / 28; int rem = tid % 28;
    int y = rem >> 1; int x0 = (rem & 1) * 7;
    float acc[4][7];
    #pragma unroll
    for (int o = 0; o < 4; o++)
        #pragma unroll
        for (int xx = 0; xx < 7; xx++) acc[o][xx] = 0.f;

    const float4* wp = (const float4*)g_W2R;   // [(ci*25+kq)*8 + ocg]
    #pragma unroll 1
    for (int ci = 0; ci < 16; ci++) {
        #pragma unroll
        for (int ky = 0; ky < 5; ky++) {
            float rin[11];
            #pragma unroll
            for (int j = 0; j < 11; j++) rin[j] = in_s[ci * 324 + (y + ky) * 18 + x0 + j];
            #pragma unroll
            for (int kx = 0; kx < 5; kx++) {
                float4 w = __ldg(&wp[(ci * 25 + ky * 5 + kx) * 8 + ocg]);
                #pragma unroll
                for (int xx = 0; xx < 7; xx++) {
                    float v = rin[kx + xx];
                    acc[0][xx] += w.x * v; acc[1][xx] += w.y * v;
                    acc[2][xx] += w.z * v; acc[3][xx] += w.w * v;
                }
            }
        }
    }
    float* dst = &g_U2[t * (NB * 6272) + b * 6272];
    #pragma unroll
    for (int o = 0; o < 4; o++)
        #pragma unroll
        for (int xx = 0; xx < 7; xx++)
            dst[(ocg * 4 + o) * 196 + y * 14 + x0 + xx] = acc[o][xx];
}

// ---------------- fc1: GEMM  C[3200,410] = S2p[3200,1568] * wf1^T --------------
__global__ void k_dense1(const float* __restrict__ wf1) {
    __shared__ float As[16][64];
    __shared__ float Bs[16][64];
    int n0 = blockIdx.x * 64;
    int m0 = blockIdx.y * 64;
    int tid = threadIdx.x;                 // 256
    int tx = tid & 15, ty = tid >> 4;
    int lm = tid >> 2;                     // 0..63
    int lk = (tid & 3) << 2;               // 0,4,8,12
    float acc[4][4];
    #pragma unroll
    for (int i2 = 0; i2 < 4; i2++)
        #pragma unroll
        for (int j = 0; j < 4; j++) acc[i2][j] = 0.f;

    const float* arow = &g_S2p[(m0 + lm) * 1568 + lk];
    int nrow = n0 + lm;
    const float* brow = (nrow < 410) ? &wf1[nrow * 1568 + lk] : 0;

    for (int kt = 0; kt < 1568; kt += 16) {
        float4 a4 = *(const float4*)(arow + kt);
        float4 b4 = brow ? *(const float4*)(brow + kt) : make_float4(0.f, 0.f, 0.f, 0.f);
        As[lk + 0][lm] = a4.x; As[lk + 1][lm] = a4.y; As[lk + 2][lm] = a4.z; As[lk + 3][lm] = a4.w;
        Bs[lk + 0][lm] = b4.x; Bs[lk + 1][lm] = b4.y; Bs[lk + 2][lm] = b4.z; Bs[lk + 3][lm] = b4.w;
        __syncthreads();
        #pragma unroll
        for (int k = 0; k < 16; k++) {
            float4 av = *(const float4*)&As[k][ty * 4];
            float4 bv = *(const float4*)&Bs[k][tx * 4];
            acc[0][0] += av.x * bv.x; acc[0][1] += av.x * bv.y; acc[0][2] += av.x * bv.z; acc[0][3] += av.x * bv.w;
            acc[1][0] += av.y * bv.x; acc[1][1] += av.y * bv.y; acc[1][2] += av.y * bv.z; acc[1][3] += av.y * bv.w;
            acc[2][0] += av.z * bv.x; acc[2][1] += av.z * bv.y; acc[2][2] += av.z * bv.z; acc[2][3] += av.z * bv.w;
            acc[3][0] += av.w * bv.x; acc[3][1] += av.w * bv.y; acc[3][2] += av.w * bv.z; acc[3][3] += av.w * bv.w;
        }
        __syncthreads();
    }
    #pragma unroll
    for (int i2 = 0; i2 < 4; i2++) {
        int m = m0 + ty * 4 + i2;
        #pragma unroll
        for (int j = 0; j < 4; j++) {
            int n = n0 + tx * 4 + j;
            if (n < 410) g_U3[m * 410 + n] = acc[i2][j];
        }
    }
}

// ---------------- fc2: [3200,10] = S3[3200,410] * wf2^T ------------------------
__global__ void k_dense2(const float* __restrict__ wf2) {
    int i = blockIdx.x * blockDim.x + threadIdx.x;
    if (i >= 32000) return;
    int m = i / 10, o = i - (i / 10) * 10;
    const float* a = &g_U3[m * 410];
    const float* w = &wf2[o * 410];
    float acc = 0.f;
    #pragma unroll 2
    for (int k = 0; k < 410; k++) acc += a[k] * w[k];
    g_U4[m * 10 + o] = acc;
}

// ---------------- final psp + spike + transpose to [b][o][t] -------------------
__global__ void k_final(float* __restrict__ out) {
    int i = threadIdx.x;                   // 320 = b*10+o
    if (i >= 320) return;
    float s1 = 0.f, s2 = 0.f;
    #pragma unroll 4
    for (int t = 0; t < T_SIM; t++) {
        float x = g_U4[t * 320 + i];
        s2 = R_DEC * (s2 + s1);
        s1 = R_DEC * s1 + x;
        out[i * T_SIM + t] = (C_EPS * s2 >= 1.0f) ? 1.0f : 0.0f;
    }
}

// -------------------------------------------------------------------------------
extern "C" void kernel_launch(void* const* d_in, const int* in_sizes, int n_in,
                              void* d_out, int out_size) {
    const float* img    = (const float*)d_in[0];
    const float* rand_u = (const float*)d_in[1];
    const float* w1     = (const float*)d_in[2];
    const float* w2     = (const float*)d_in[3];
    const float* wf1    = (const float*)d_in[4];
    const float* wf2    = (const float*)d_in[5];
    float* out = (float*)d_out;

    void *pU1, *pU2, *pU3, *pS1p, *pS2p;
    cudaGetSymbolAddress(&pU1,  g_U1);
    cudaGetSymbolAddress(&pU2,  g_U2);
    cudaGetSymbolAddress(&pU3,  g_U3);
    cudaGetSymbolAddress(&pS1p, g_S1p);
    cudaGetSymbolAddress(&pS2p, g_S2p);

    k_encode<<<9800, 256>>>(rand_u, img);
    k_reorder<<<50, 256>>>(w1, w2);

    k_conv1<<<3200, 448>>>();
    // fused psp+spike+pool+psp+spike, layer 1: U1[.,16,28,28] -> S1p[.,16,14,14]
    k_fused_pp<<<392, 256>>>((const float*)pU1, (float*)pS1p,
                             28, NB * 16 * 784, NB * 16 * 196, NB * 16 * 196);

    k_conv2<<<3200, 224>>>();
    // fused chain, layer 2: U2[.,32,14,14] -> S2p[.,32,7,7]
    k_fused_pp<<<196, 256>>>((const float*)pU2, (float*)pS2p,
                             14, NB * 32 * 196, NB * 1568, NB * 1568);

    dim3 g1(7, 50);
    k_dense1<<<g1, 256>>>(wf1);
    k_psp<<<52, 256>>>((float*)pU3, NB * 410);                              // -> S3

    k_dense2<<<125, 256>>>(wf2);
    k_final<<<1, 320>>>(out);
}

// round 5
// speedup vs baseline: 1.0202x; 1.0202x over previous
#include <cuda_runtime.h>

#define T_SIM 100
#define NB 32
// e^{-1/tau}, tau = 10
#define R_DEC 0.9048374180359595f
// e/tau
#define C_EPS 0.2718281828459045f

typedef unsigned long long u64;

// ---- packed fp32x2 helpers (Blackwell FFMA2; exact fp32 semantics) -----------
__device__ __forceinline__ u64 pack2(float lo, float hi) {
    u64 r;
    asm("mov.b64 %0, {%1, %2};" : "=l"(r) : "f"(lo), "f"(hi));
    return r;
}
__device__ __forceinline__ u64 bcast2(float v) { return pack2(v, v); }
__device__ __forceinline__ u64 ffma2(u64 a, u64 b, u64 c) {
    u64 d;
    asm("fma.rn.f32x2 %0, %1, %2, %3;" : "=l"(d) : "l"(a), "l"(b), "l"(c));
    return d;
}
__device__ __forceinline__ void unpack2(u64 v, float& lo, float& hi) {
    asm("mov.b64 {%0, %1}, %2;" : "=f"(lo), "=f"(hi) : "l"(v));
}

// ---------------- scratch (device globals; no allocation allowed) -------------
__device__ float g_S0 [T_SIM * NB * 784];          // spikes in   [t][b][28][28]
__device__ float g_U1 [T_SIM * NB * 16 * 784];     // conv1 raw membrane input
__device__ float g_S1p[T_SIM * NB * 16 * 196];     // fused chain out (layer1)
__device__ float g_U2 [T_SIM * NB * 32 * 196];     // conv2 raw membrane input
__device__ float g_S2p[T_SIM * NB * 1568];         // fused chain out (A matrix of fc1)
__device__ float g_U3 [T_SIM * NB * 410];          // fc1 out -> spikes (in place)
__device__ float g_U4 [T_SIM * NB * 10];           // fc2 out
__device__ float g_W1R[400];                        // w1 reordered [kq][oc]
__device__ float g_W2R[12800];                      // w2 reordered [ci*25+kq][oc]

// ---------------- encode: bernoulli spikes, smem tile transpose ----------------
__global__ void k_encode(const float* __restrict__ rand_u, const float* __restrict__ img) {
    __shared__ float tile[32][101];
    __shared__ float imgs[32];
    int bp0 = blockIdx.x * 32;
    int tid = threadIdx.x;                 // 256
    if (tid < 32) imgs[tid] = img[bp0 + tid];
    for (int idx = tid; idx < 3200; idx += 256) {
        int bl = idx / 100, t = idx - bl * 100;
        tile[bl][t] = rand_u[(bp0 + bl) * 100 + t];   // coalesced runs of 100
    }
    __syncthreads();
    for (int idx = tid; idx < 3200; idx += 256) {
        int t = idx >> 5, bl = idx & 31;
        g_S0[t * 25088 + bp0 + bl] = (tile[bl][t] < imgs[bl]) ? 1.0f : 0.0f;  // coalesced
    }
}

// ---------------- weight reorder (oc innermost for vector loads) --------------
__global__ void k_reorder(const float* __restrict__ w1, const float* __restrict__ w2) {
    int i = blockIdx.x * blockDim.x + threadIdx.x;
    if (i < 400) {
        int oc = i & 15, kq = i >> 4;
        g_W1R[i] = w1[oc * 25 + kq];
    }
    if (i < 12800) {
        int oc = i & 31, kk = i >> 5;
        int ci = kk / 25, kq = kk % 25;
        g_W2R[i] = w2[(oc * 16 + ci) * 25 + kq];
    }
}

// ---------------- conv1: 1->16ch, 28x28, 5x5 pad2, per (t,b) plane -------------
__global__ void k_conv1() {
    __shared__ float in_s[32 * 32];   // padded 28+4
    __shared__ float w_s[400];
    int tb = blockIdx.x; int t = tb >> 5, b = tb & 31;
    int tid = threadIdx.x;            // 448 threads
    for (int i = tid; i < 1024; i += blockDim.x) in_s[i] = 0.f;
    __syncthreads();
    const float* src = &g_S0[t * (NB * 784) + b * 784];
    for (int i = tid; i < 784; i += blockDim.x) {
        int y = i / 28, x = i - y * 28;
        in_s[(y + 2) * 32 + (x + 2)] = src[i];
    }
    for (int i = tid; i < 400; i += blockDim.x) w_s[i] = g_W1R[i];
    __syncthreads();

    int ocg = tid / 112; int rem = tid % 112;
    int y = rem >> 2; int x0 = (rem & 3) * 7;
    u64 acc2[2][7];
    #pragma unroll
    for (int p = 0; p < 2; p++)
        #pragma unroll
        for (int xx = 0; xx < 7; xx++) acc2[p][xx] = 0ull;

    const u64* ws2 = (const u64*)w_s;     // pairs (oc even, oc odd)
    #pragma unroll
    for (int ky = 0; ky < 5; ky++) {
        float rin[11]; u64 vb[11];
        #pragma unroll
        for (int j = 0; j < 11; j++) {
            rin[j] = in_s[(y + ky) * 32 + x0 + j];
            vb[j]  = bcast2(rin[j]);
        }
        #pragma unroll
        for (int kx = 0; kx < 5; kx++) {
            int wi = (ky * 5 + kx) * 8 + ocg * 2;
            u64 w01 = ws2[wi], w23 = ws2[wi + 1];
            #pragma unroll
            for (int xx = 0; xx < 7; xx++) {
                acc2[0][xx] = ffma2(w01, vb[kx + xx], acc2[0][xx]);
                acc2[1][xx] = ffma2(w23, vb[kx + xx], acc2[1][xx]);
            }
        }
    }
    float* dst = &g_U1[t * (NB * 12544) + b * 12544];
    #pragma unroll
    for (int p = 0; p < 2; p++)
        #pragma unroll
        for (int xx = 0; xx < 7; xx++) {
            float lo, hi; unpack2(acc2[p][xx], lo, hi);
            dst[(ocg * 4 + 2 * p + 0) * 784 + y * 28 + x0 + xx] = lo;
            dst[(ocg * 4 + 2 * p + 1) * 784 + y * 28 + x0 + xx] = hi;
        }
}

// ------- fused: psp+spike (full res) -> 2x2 pool(x1.1) -> psp+spike ------------
__global__ void k_fused_pp(const float* __restrict__ uin, float* __restrict__ sout,
                           int Hin, int planeIn, int planeOut, int total) {
    int i = blockIdx.x * blockDim.x + threadIdx.x;
    if (i >= total) return;
    int ho = Hin >> 1;
    int x  = i % ho;
    int y  = (i / ho) % ho;
    int bc = i / (ho * ho);
    const float* base = uin + bc * Hin * Hin + (2 * y) * Hin + 2 * x;

    float a1 = 0.f, a2 = 0.f, b1 = 0.f, b2 = 0.f;
    float c1 = 0.f, c2 = 0.f, d1 = 0.f, d2 = 0.f;
    float o1 = 0.f, o2 = 0.f;

    #pragma unroll 4
    for (int t = 0; t < T_SIM; t++) {
        float2 top = *(const float2*)(base + (size_t)t * planeIn);
        float2 bot = *(const float2*)(base + (size_t)t * planeIn + Hin);

        a2 = R_DEC * (a2 + a1); a1 = R_DEC * a1 + top.x;
        b2 = R_DEC * (b2 + b1); b1 = R_DEC * b1 + top.y;
        c2 = R_DEC * (c2 + c1); c1 = R_DEC * c1 + bot.x;
        d2 = R_DEC * (d2 + d1); d1 = R_DEC * d1 + bot.y;

        float spkA = (C_EPS * a2 >= 1.0f) ? 1.0f : 0.0f;
        float spkB = (C_EPS * b2 >= 1.0f) ? 1.0f : 0.0f;
        float spkC = (C_EPS * c2 >= 1.0f) ? 1.0f : 0.0f;
        float spkD = (C_EPS * d2 >= 1.0f) ? 1.0f : 0.0f;
        float pool = 1.1f * ((spkA + spkB) + (spkC + spkD));

        o2 = R_DEC * (o2 + o1); o1 = R_DEC * o1 + pool;
        sout[(size_t)t * planeOut + i] = (C_EPS * o2 >= 1.0f) ? 1.0f : 0.0f;
    }
}

// ---------------- generic psp + spike (in place, scan over t) ------------------
__global__ void k_psp(float* __restrict__ u, int plane) {
    int i = blockIdx.x * blockDim.x + threadIdx.x;
    if (i >= plane) return;
    float* p = u + i;
    float s1 = 0.f, s2 = 0.f;
    #pragma unroll 4
    for (int t = 0; t < T_SIM; t++) {
        float x = p[(size_t)t * plane];
        s2 = R_DEC * (s2 + s1);
        s1 = R_DEC * s1 + x;
        p[(size_t)t * plane] = (C_EPS * s2 >= 1.0f) ? 1.0f : 0.0f;
    }
}

// ---------------- conv2: 16->32ch, 14x14, 5x5 pad2, per (t,b) plane ------------
__global__ void k_conv2() {
    __shared__ float in_s[16 * 18 * 18];   // 5184 floats, padded 14+4
    int tb = blockIdx.x; int t = tb >> 5, b = tb & 31;
    int tid = threadIdx.x;                 // 224 threads
    for (int i = tid; i < 5184; i += blockDim.x) in_s[i] = 0.f;
    __syncthreads();
    const float* src = &g_S1p[t * (NB * 3136) + b * 3136];
    for (int i = tid; i < 3136; i += blockDim.x) {
        int ci = i / 196, r = i - ci * 196;
        int y = r / 14, x = r - y * 14;
        in_s[ci * 324 + (y + 2) * 18 + (x + 2)] = src[i];
    }
    __syncthreads();

    int ocg = tid / 28; int rem = tid % 28;
    int y = rem >> 1; int x0 = (rem & 1) * 7;
    u64 acc2[2][7];
    #pragma unroll
    for (int p = 0; p < 2; p++)
        #pragma unroll
        for (int xx = 0; xx < 7; xx++) acc2[p][xx] = 0ull;

    const u64* wp2 = (const u64*)g_W2R;    // pairs: idx = (ci*25+kq)*16 + ocg*2
    #pragma unroll 1
    for (int ci = 0; ci < 16; ci++) {
        #pragma unroll
        for (int ky = 0; ky < 5; ky++) {
            float rin[11]; u64 vb[11];
            #pragma unroll
            for (int j = 0; j < 11; j++) {
                rin[j] = in_s[ci * 324 + (y + ky) * 18 + x0 + j];
                vb[j]  = bcast2(rin[j]);
            }
            #pragma unroll
            for (int kx = 0; kx < 5; kx++) {
                int wi = (ci * 25 + ky * 5 + kx) * 16 + ocg * 2;
                u64 w01 = __ldg(&wp2[wi]);
                u64 w23 = __ldg(&wp2[wi + 1]);
                #pragma unroll
                for (int xx = 0; xx < 7; xx++) {
                    acc2[0][xx] = ffma2(w01, vb[kx + xx], acc2[0][xx]);
                    acc2[1][xx] = ffma2(w23, vb[kx + xx], acc2[1][xx]);
                }
            }
        }
    }
    float* dst = &g_U2[t * (NB * 6272) + b * 6272];
    #pragma unroll
    for (int p = 0; p < 2; p++)
        #pragma unroll
        for (int xx = 0; xx < 7; xx++) {
            float lo, hi; unpack2(acc2[p][xx], lo, hi);
            dst[(ocg * 4 + 2 * p + 0) * 196 + y * 14 + x0 + xx] = lo;
            dst[(ocg * 4 + 2 * p + 1) * 196 + y * 14 + x0 + xx] = hi;
        }
}

// ---------------- fc1: GEMM  C[3200,410] = S2p[3200,1568] * wf1^T --------------
__global__ void k_dense1(const float* __restrict__ wf1) {
    __shared__ float As[16][64];
    __shared__ float Bs[16][64];
    int n0 = blockIdx.x * 64;
    int m0 = blockIdx.y * 64;
    int tid = threadIdx.x;                 // 256
    int tx = tid & 15, ty = tid >> 4;
    int lm = tid >> 2;                     // 0..63
    int lk = (tid & 3) << 2;               // 0,4,8,12
    u64 acc2[4][2];
    #pragma unroll
    for (int i2 = 0; i2 < 4; i2++) { acc2[i2][0] = 0ull; acc2[i2][1] = 0ull; }

    const float* arow = &g_S2p[(m0 + lm) * 1568 + lk];
    int nrow = n0 + lm;
    const float* brow = (nrow < 410) ? &wf1[nrow * 1568 + lk] : 0;

    for (int kt = 0; kt < 1568; kt += 16) {
        float4 a4 = *(const float4*)(arow + kt);
        float4 b4 = brow ? *(const float4*)(brow + kt) : make_float4(0.f, 0.f, 0.f, 0.f);
        As[lk + 0][lm] = a4.x; As[lk + 1][lm] = a4.y; As[lk + 2][lm] = a4.z; As[lk + 3][lm] = a4.w;
        Bs[lk + 0][lm] = b4.x; Bs[lk + 1][lm] = b4.y; Bs[lk + 2][lm] = b4.z; Bs[lk + 3][lm] = b4.w;
        __syncthreads();
        #pragma unroll
        for (int k = 0; k < 16; k++) {
            float4 av = *(const float4*)&As[k][ty * 4];
            const u64* bp = (const u64*)&Bs[k][tx * 4];
            u64 b01 = bp[0], b23 = bp[1];
            u64 va0 = bcast2(av.x), va1 = bcast2(av.y), va2 = bcast2(av.z), va3 = bcast2(av.w);
            acc2[0][0] = ffma2(va0, b01, acc2[0][0]); acc2[0][1] = ffma2(va0, b23, acc2[0][1]);
            acc2[1][0] = ffma2(va1, b01, acc2[1][0]); acc2[1][1] = ffma2(va1, b23, acc2[1][1]);
            acc2[2][0] = ffma2(va2, b01, acc2[2][0]); acc2[2][1] = ffma2(va2, b23, acc2[2][1]);
            acc2[3][0] = ffma2(va3, b01, acc2[3][0]); acc2[3][1] = ffma2(va3, b23, acc2[3][1]);
        }
        __syncthreads();
    }
    #pragma unroll
    for (int i2 = 0; i2 < 4; i2++) {
        int m = m0 + ty * 4 + i2;
        float c0, c1, c2, c3;
        unpack2(acc2[i2][0], c0, c1);
        unpack2(acc2[i2][1], c2, c3);
        int n = n0 + tx * 4;
        if (n + 0 < 410) g_U3[m * 410 + n + 0] = c0;
        if (n + 1 < 410) g_U3[m * 410 + n + 1] = c1;
        if (n + 2 < 410) g_U3[m * 410 + n + 2] = c2;
        if (n + 3 < 410) g_U3[m * 410 + n + 3] = c3;
    }
}

// ---------------- fc2: [3200,10] = S3[3200,410] * wf2^T ------------------------
__global__ void k_dense2(const float* __restrict__ wf2) {
    int i = blockIdx.x * blockDim.x + threadIdx.x;
    if (i >= 32000) return;
    int m = i / 10, o = i - (i / 10) * 10;
    const float* a = &g_U3[m * 410];
    const float* w = &wf2[o * 410];
    float acc = 0.f;
    #pragma unroll 2
    for (int k = 0; k < 410; k++) acc += a[k] * w[k];
    g_U4[m * 10 + o] = acc;
}

// ---------------- final psp + spike + transpose to [b][o][t] -------------------
__global__ void k_final(float* __restrict__ out) {
    int i = threadIdx.x;                   // 320 = b*10+o
    if (i >= 320) return;
    float s1 = 0.f, s2 = 0.f;
    #pragma unroll 4
    for (int t = 0; t < T_SIM; t++) {
        float x = g_U4[t * 320 + i];
        s2 = R_DEC * (s2 + s1);
        s1 = R_DEC * s1 + x;
        out[i * T_SIM + t] = (C_EPS * s2 >= 1.0f) ? 1.0f : 0.0f;
    }
}

// -------------------------------------------------------------------------------
extern "C" void kernel_launch(void* const* d_in, const int* in_sizes, int n_in,
                              void* d_out, int out_size) {
    const float* img    = (const float*)d_in[0];
    const float* rand_u = (const float*)d_in[1];
    const float* w1     = (const float*)d_in[2];
    const float* w2     = (const float*)d_in[3];
    const float* wf1    = (const float*)d_in[4];
    const float* wf2    = (const float*)d_in[5];
    float* out = (float*)d_out;

    void *pU1, *pU2, *pU3, *pS1p, *pS2p;
    cudaGetSymbolAddress(&pU1,  g_U1);
    cudaGetSymbolAddress(&pU2,  g_U2);
    cudaGetSymbolAddress(&pU3,  g_U3);
    cudaGetSymbolAddress(&pS1p, g_S1p);
    cudaGetSymbolAddress(&pS2p, g_S2p);

    k_encode<<<784, 256>>>(rand_u, img);
    k_reorder<<<50, 256>>>(w1, w2);

    k_conv1<<<3200, 448>>>();
    k_fused_pp<<<392, 256>>>((const float*)pU1, (float*)pS1p,
                             28, NB * 16 * 784, NB * 16 * 196, NB * 16 * 196);

    k_conv2<<<3200, 224>>>();
    k_fused_pp<<<196, 256>>>((const float*)pU2, (float*)pS2p,
                             14, NB * 32 * 196, NB * 1568, NB * 1568);

    dim3 g1(7, 50);
    k_dense1<<<g1, 256>>>(wf1);
    k_psp<<<52, 256>>>((float*)pU3, NB * 410);                              // -> S3

    k_dense2<<<125, 256>>>(wf2);
    k_final<<<1, 320>>>(out);
}

// round 7
// speedup vs baseline: 1.2688x; 1.2436x over previous
#include <cuda_runtime.h>
#include <cuda_bf16.h>

#define T_SIM 100
#define NB 32
// e^{-1/tau}, tau = 10
#define R_DEC 0.9048374180359595f
// e/tau
#define C_EPS 0.2718281828459045f

typedef unsigned int u32;
typedef unsigned short u16;

// ---------------- scratch (device globals; no allocation allowed) -------------
__device__ float g_S0 [T_SIM * NB * 784];            // spikes in   [t][b][28][28]
__device__ float g_U1 [T_SIM * NB * 16 * 784];       // conv1 raw membrane input
__device__ __nv_bfloat16 g_S1p[T_SIM * NB * 16 * 196]; // layer1 spikes (bf16, exact 0/1)
__device__ float g_U2 [T_SIM * NB * 32 * 196];       // conv2 raw membrane input
__device__ float g_S2p[T_SIM * NB * 1568];           // layer2 spikes (A matrix of fc1)
__device__ float g_U3 [T_SIM * NB * 410];            // fc1 out -> spikes (in place)
__device__ float g_U4 [T_SIM * NB * 10];             // fc2 out
__device__ float g_W1R[400];                          // w1 reordered [kq][oc]
__device__ u16   g_W2L[25 * 3 * 32 * 16];             // w2 bf16 limbs [kq][limb][oc][ci]

// ---------------- encode: bernoulli spikes, smem tile transpose ----------------
__global__ void k_encode(const float* __restrict__ rand_u, const float* __restrict__ img) {
    __shared__ float tile[32][101];
    __shared__ float imgs[32];
    int bp0 = blockIdx.x * 32;
    int tid = threadIdx.x;                 // 256
    if (tid < 32) imgs[tid] = img[bp0 + tid];
    for (int idx = tid; idx < 3200; idx += 256) {
        int bl = idx / 100, t = idx - bl * 100;
        tile[bl][t] = rand_u[(bp0 + bl) * 100 + t];   // coalesced runs of 100
    }
    __syncthreads();
    for (int idx = tid; idx < 3200; idx += 256) {
        int t = idx >> 5, bl = idx & 31;
        g_S0[t * 25088 + bp0 + bl] = (tile[bl][t] < imgs[bl]) ? 1.0f : 0.0f;  // coalesced
    }
}

// ------- weight prep: w1 reorder + exact 3-limb bf16 split of w2 ---------------
__global__ void k_reorder(const float* __restrict__ w1, const float* __restrict__ w2) {
    int i = blockIdx.x * blockDim.x + threadIdx.x;
    if (i < 400) {
        int oc = i & 15, kq = i >> 4;
        g_W1R[i] = w1[oc * 25 + kq];
    }
    if (i < 38400) {   // [kq][l][oc][ci]
        int ci = i & 15;
        int oc = (i >> 4) & 31;
        int l  = (i >> 9) % 3;
        int kq = i / 1536;
        float w = w2[oc * 400 + ci * 25 + kq];
        u32 u0 = __float_as_uint(w);
        float h1 = __uint_as_float(u0 & 0xFFFF0000u);
        float r1 = w - h1;                       // exact
        u32 u1 = __float_as_uint(r1);
        float h2 = __uint_as_float(u1 & 0xFFFF0000u);
        float r2 = r1 - h2;                      // exact, <=8 significant bits
        u32 u2r = __float_as_uint(r2);
        u16 s = (l == 0) ? (u16)(u0 >> 16) : (l == 1) ? (u16)(u1 >> 16) : (u16)(u2r >> 16);
        g_W2L[i] = s;
    }
}

// ---------------- conv1: 1->16ch, 28x28, 5x5 pad2, per (t,b) plane -------------
__global__ void k_conv1() {
    __shared__ float in_s[32 * 32];   // padded 28+4
    __shared__ float w_s[400];
    int tb = blockIdx.x; int t = tb >> 5, b = tb & 31;
    int tid = threadIdx.x;            // 448 threads
    for (int i = tid; i < 1024; i += blockDim.x) in_s[i] = 0.f;
    __syncthreads();
    const float* src = &g_S0[t * (NB * 784) + b * 784];
    for (int i = tid; i < 784; i += blockDim.x) {
        int y = i / 28, x = i - y * 28;
        in_s[(y + 2) * 32 + (x + 2)] = src[i];
    }
    for (int i = tid; i < 400; i += blockDim.x) w_s[i] = g_W1R[i];
    __syncthreads();

    int ocg = tid / 112; int rem = tid % 112;
    int y = rem >> 2; int x0 = (rem & 3) * 7;
    float acc[4][7];
    #pragma unroll
    for (int o = 0; o < 4; o++)
        #pragma unroll
        for (int xx = 0; xx < 7; xx++) acc[o][xx] = 0.f;

    #pragma unroll
    for (int ky = 0; ky < 5; ky++) {
        float rin[11];
        #pragma unroll
        for (int j = 0; j < 11; j++) rin[j] = in_s[(y + ky) * 32 + x0 + j];
        #pragma unroll
        for (int kx = 0; kx < 5; kx++) {
            float4 w = *(const float4*)&w_s[(ky * 5 + kx) * 16 + ocg * 4];
            #pragma unroll
            for (int xx = 0; xx < 7; xx++) {
                float v = rin[kx + xx];
                acc[0][xx] += w.x * v; acc[1][xx] += w.y * v;
                acc[2][xx] += w.z * v; acc[3][xx] += w.w * v;
            }
        }
    }
    float* dst = &g_U1[t * (NB * 12544) + b * 12544];
    #pragma unroll
    for (int o = 0; o < 4; o++)
        #pragma unroll
        for (int xx = 0; xx < 7; xx++)
            dst[(ocg * 4 + o) * 784 + y * 28 + x0 + xx] = acc[o][xx];
}

// ------- fused: psp+spike (full res) -> 2x2 pool(x1.1) -> psp+spike ------------
template <typename TOut>
__global__ void k_fused_pp(const float* __restrict__ uin, TOut* __restrict__ sout,
                           int Hin, int planeIn, int planeOut, int total) {
    int i = blockIdx.x * blockDim.x + threadIdx.x;
    if (i >= total) return;
    int ho = Hin >> 1;
    int x  = i % ho;
    int y  = (i / ho) % ho;
    int bc = i / (ho * ho);
    const float* base = uin + bc * Hin * Hin + (2 * y) * Hin + 2 * x;

    float a1 = 0.f, a2 = 0.f, b1 = 0.f, b2 = 0.f;
    float c1 = 0.f, c2 = 0.f, d1 = 0.f, d2 = 0.f;
    float o1 = 0.f, o2 = 0.f;

    #pragma unroll 4
    for (int t = 0; t < T_SIM; t++) {
        float2 top = *(const float2*)(base + (size_t)t * planeIn);
        float2 bot = *(const float2*)(base + (size_t)t * planeIn + Hin);

        a2 = R_DEC * (a2 + a1); a1 = R_DEC * a1 + top.x;
        b2 = R_DEC * (b2 + b1); b1 = R_DEC * b1 + top.y;
        c2 = R_DEC * (c2 + c1); c1 = R_DEC * c1 + bot.x;
        d2 = R_DEC * (d2 + d1); d1 = R_DEC * d1 + bot.y;

        float spkA = (C_EPS * a2 >= 1.0f) ? 1.0f : 0.0f;
        float spkB = (C_EPS * b2 >= 1.0f) ? 1.0f : 0.0f;
        float spkC = (C_EPS * c2 >= 1.0f) ? 1.0f : 0.0f;
        float spkD = (C_EPS * d2 >= 1.0f) ? 1.0f : 0.0f;
        float pool = 1.1f * ((spkA + spkB) + (spkC + spkD));

        o2 = R_DEC * (o2 + o1); o1 = R_DEC * o1 + pool;
        sout[(size_t)t * planeOut + i] = (TOut)((C_EPS * o2 >= 1.0f) ? 1.0f : 0.0f);
    }
}

// ---------------- generic psp + spike (in place, scan over t) ------------------
__global__ void k_psp(float* __restrict__ u, int plane) {
    int i = blockIdx.x * blockDim.x + threadIdx.x;
    if (i >= plane) return;
    float* p = u + i;
    float s1 = 0.f, s2 = 0.f;
    #pragma unroll 4
    for (int t = 0; t < T_SIM; t++) {
        float x = p[(size_t)t * plane];
        s2 = R_DEC * (s2 + s1);
        s1 = R_DEC * s1 + x;
        p[(size_t)t * plane] = (C_EPS * s2 >= 1.0f) ? 1.0f : 0.0f;
    }
}

// ---- conv2 via tensor cores: shift-decomposed implicit GEMM, exact bf16 limbs --
// One (t,b) plane per block, 256 threads = 8 warps.
// D[oc 32][pix 14x16pad] = sum_{kq,ci} W[oc][ci][kq] * S[ci][shifted pix]
// A (16x16) = weight limb [oc rows][ci cols]; B (16x8) = spikes [ci rows][pix cols].
__device__ __forceinline__ void mma16816(float* c, const u32* a, u32 b0, u32 b1) {
    asm volatile(
        "mma.sync.aligned.m16n8k16.row.col.f32.bf16.bf16.f32 "
        "{%0,%1,%2,%3}, {%4,%5,%6,%7}, {%8,%9}, {%0,%1,%2,%3};"
        : "+f"(c[0]), "+f"(c[1]), "+f"(c[2]), "+f"(c[3])
        : "r"(a[0]), "r"(a[1]), "r"(a[2]), "r"(a[3]), "r"(b0), "r"(b1));
}

__global__ __launch_bounds__(256) void k_conv2_mma() {
    __shared__ __nv_bfloat16 in_s[18 * 24 * 16];   // [row][col][ci], 13824 B
    int tb = blockIdx.x; int t = tb >> 5, b = tb & 31;
    int tid = threadIdx.x, warp = tid >> 5, lane = tid & 31;

    u32* z = (u32*)in_s;
    for (int i = tid; i < 3456; i += 256) z[i] = 0u;
    __syncthreads();
    const __nv_bfloat16* src = g_S1p + (size_t)t * (NB * 3136) + b * 3136;
    for (int i = tid; i < 3136; i += 256) {
        int ci = i / 196, p = i - ci * 196;
        int y = p / 14, x = p - y * 14;
        in_s[((y + 2) * 24 + (x + 2)) * 16 + ci] = src[i];
    }
    __syncthreads();

    int g  = lane >> 2;          // 0..7
    int tq = lane & 3;           // 0..3
    int m  = warp >> 2;          // oc half: 0 or 1
    int nr0 = (warp & 3) * 7;    // 7 n-tiles per warp (n-tile = (y, x-half))

    float acc[7][4];
    #pragma unroll
    for (int j = 0; j < 7; j++)
        #pragma unroll
        for (int q = 0; q < 4; q++) acc[j][q] = 0.f;

    const u32* wl = (const u32*)g_W2L;   // [kq][l][oc][ci/2] u32 pairs

    for (int kq = 0; kq < 25; kq++) {
        int ky = kq / 5, kx = kq - ky * 5;
        u32 af[3][4];
        #pragma unroll
        for (int l = 0; l < 3; l++) {
            int base = ((kq * 3 + l) * 32 + m * 16 + g) * 8;
            af[l][0] = __ldg(&wl[base + tq]);          // row g,   ci pair tq
            af[l][1] = __ldg(&wl[base + 64 + tq]);     // row g+8
            af[l][2] = __ldg(&wl[base + tq + 4]);      // ci pair tq+4 (ci 8..15)
            af[l][3] = __ldg(&wl[base + 64 + tq + 4]);
        }
        #pragma unroll
        for (int j = 0; j < 7; j++) {
            int nr = nr0 + j;
            int y = nr >> 1, xh = (nr & 1) * 8;
            const u32* bp = (const u32*)&in_s[((y + ky) * 24 + (xh + g + kx)) * 16 + tq * 2];
            u32 b0 = bp[0];      // ci 2tq, 2tq+1
            u32 b1 = bp[4];      // ci 2tq+8, 2tq+9
            mma16816(acc[j], af[0], b0, b1);
            mma16816(acc[j], af[1], b0, b1);
            mma16816(acc[j], af[2], b0, b1);
        }
    }

    float* dst = g_U2 + (size_t)t * (NB * 6272) + b * 6272;
    int oc0 = m * 16 + g;
    int xp0 = tq * 2;
    #pragma unroll
    for (int j = 0; j < 7; j++) {
        int nr = nr0 + j;
        int y = nr >> 1, xh = (nr & 1) * 8;
        int xp = xh + xp0;
        if (xp <= 12) {          // xp,xp+1 both < 14
            float2 v0; v0.x = acc[j][0]; v0.y = acc[j][1];
            float2 v1; v1.x = acc[j][2]; v1.y = acc[j][3];
            *(float2*)&dst[oc0 * 196 + y * 14 + xp] = v0;
            *(float2*)&dst[(oc0 + 8) * 196 + y * 14 + xp] = v1;
        }
    }
}

// ---------------- fc1: GEMM  C[3200,410] = S2p[3200,1568] * wf1^T --------------
__global__ void k_dense1(const float* __restrict__ wf1) {
    __shared__ float As[16][64];
    __shared__ float Bs[16][64];
    int n0 = blockIdx.x * 64;
    int m0 = blockIdx.y * 64;
    int tid = threadIdx.x;                 // 256
    int tx = tid & 15, ty = tid >> 4;
    int lm = tid >> 2;                     // 0..63
    int lk = (tid & 3) << 2;               // 0,4,8,12
    float acc[4][4];
    #pragma unroll
    for (int i2 = 0; i2 < 4; i2++)
        #pragma unroll
        for (int j = 0; j < 4; j++) acc[i2][j] = 0.f;

    const float* arow = &g_S2p[(m0 + lm) * 1568 + lk];
    int nrow = n0 + lm;
    const float* brow = (nrow < 410) ? &wf1[nrow * 1568 + lk] : 0;

    for (int kt = 0; kt < 1568; kt += 16) {
        float4 a4 = *(const float4*)(arow + kt);
        float4 b4 = brow ? *(const float4*)(brow + kt) : make_float4(0.f, 0.f, 0.f, 0.f);
        As[lk + 0][lm] = a4.x; As[lk + 1][lm] = a4.y; As[lk + 2][lm] = a4.z; As[lk + 3][lm] = a4.w;
        Bs[lk + 0][lm] = b4.x; Bs[lk + 1][lm] = b4.y; Bs[lk + 2][lm] = b4.z; Bs[lk + 3][lm] = b4.w;
        __syncthreads();
        #pragma unroll
        for (int k = 0; k < 16; k++) {
            float4 av = *(const float4*)&As[k][ty * 4];
            float4 bv = *(const float4*)&Bs[k][tx * 4];
            acc[0][0] += av.x * bv.x; acc[0][1] += av.x * bv.y; acc[0][2] += av.x * bv.z; acc[0][3] += av.x * bv.w;
            acc[1][0] += av.y * bv.x; acc[1][1] += av.y * bv.y; acc[1][2] += av.y * bv.z; acc[1][3] += av.y * bv.w;
            acc[2][0] += av.z * bv.x; acc[2][1] += av.z * bv.y; acc[2][2] += av.z * bv.z; acc[2][3] += av.z * bv.w;
            acc[3][0] += av.w * bv.x; acc[3][1] += av.w * bv.y; acc[3][2] += av.w * bv.z; acc[3][3] += av.w * bv.w;
        }
        __syncthreads();
    }
    #pragma unroll
    for (int i2 = 0; i2 < 4; i2++) {
        int m = m0 + ty * 4 + i2;
        #pragma unroll
        for (int j = 0; j < 4; j++) {
            int n = n0 + tx * 4 + j;
            if (n < 410) g_U3[m * 410 + n] = acc[i2][j];
        }
    }
}

// ---------------- fc2: [3200,10] = S3[3200,410] * wf2^T ------------------------
__global__ void k_dense2(const float* __restrict__ wf2) {
    int i = blockIdx.x * blockDim.x + threadIdx.x;
    if (i >= 32000) return;
    int m = i / 10, o = i - (i / 10) * 10;
    const float* a = &g_U3[m * 410];
    const float* w = &wf2[o * 410];
    float acc = 0.f;
    #pragma unroll 2
    for (int k = 0; k < 410; k++) acc += a[k] * w[k];
    g_U4[m * 10 + o] = acc;
}

// ---------------- final psp + spike + transpose to [b][o][t] -------------------
__global__ void k_final(float* __restrict__ out) {
    int i = threadIdx.x;                   // 320 = b*10+o
    if (i >= 320) return;
    float s1 = 0.f, s2 = 0.f;
    #pragma unroll 4
    for (int t = 0; t < T_SIM; t++) {
        float x = g_U4[t * 320 + i];
        s2 = R_DEC * (s2 + s1);
        s1 = R_DEC * s1 + x;
        out[i * T_SIM + t] = (C_EPS * s2 >= 1.0f) ? 1.0f : 0.0f;
    }
}

// -------------------------------------------------------------------------------
extern "C" void kernel_launch(void* const* d_in, const int* in_sizes, int n_in,
                              void* d_out, int out_size) {
    const float* img    = (const float*)d_in[0];
    const float* rand_u = (const float*)d_in[1];
    const float* w1     = (const float*)d_in[2];
    const float* w2     = (const float*)d_in[3];
    const float* wf1    = (const float*)d_in[4];
    const float* wf2    = (const float*)d_in[5];
    float* out = (float*)d_out;

    void *pU1, *pU2, *pU3, *pS1p, *pS2p;
    cudaGetSymbolAddress(&pU1,  g_U1);
    cudaGetSymbolAddress(&pU2,  g_U2);
    cudaGetSymbolAddress(&pU3,  g_U3);
    cudaGetSymbolAddress(&pS1p, g_S1p);
    cudaGetSymbolAddress(&pS2p, g_S2p);

    k_encode<<<784, 256>>>(rand_u, img);
    k_reorder<<<150, 256>>>(w1, w2);

    k_conv1<<<3200, 448>>>();
    // fused psp+spike+pool+psp+spike, layer 1 -> bf16 spikes for tensor-core conv2
    k_fused_pp<__nv_bfloat16><<<392, 256>>>((const float*)pU1, (__nv_bfloat16*)pS1p,
                             28, NB * 16 * 784, NB * 16 * 196, NB * 16 * 196);

    k_conv2_mma<<<3200, 256>>>();
    k_fused_pp<float><<<196, 256>>>((const float*)pU2, (float*)pS2p,
                             14, NB * 32 * 196, NB * 1568, NB * 1568);

    dim3 g1(7, 50);
    k_dense1<<<g1, 256>>>(wf1);
    k_psp<<<52, 256>>>((float*)pU3, NB * 410);                              // -> S3

    k_dense2<<<125, 256>>>(wf2);
    k_final<<<1, 320>>>(out);
}

// round 12
// speedup vs baseline: 1.6741x; 1.3194x over previous
#include <cuda_runtime.h>
#include <cuda_bf16.h>

#define T_SIM 100
#define NB 32
// e^{-1/tau}, tau = 10
#define R_DEC 0.9048374180359595f
// e/tau
#define C_EPS 0.2718281828459045f

typedef unsigned int u32;
typedef unsigned short u16;

// ---------------- scratch (device globals; no allocation allowed) -------------
__device__ float g_S0 [T_SIM * NB * 784];              // encode spikes -> P0 (in place)
__device__ float g_U1 [T_SIM * NB * 16 * 196];         // pooled pre-psp (layer1)
__device__ __nv_bfloat16 g_S1p[T_SIM * NB * 16 * 196]; // layer1 spikes (bf16 exact)
__device__ float g_U2 [T_SIM * NB * 32 * 196];         // conv2 raw membrane input
__device__ __nv_bfloat16 g_S2p[T_SIM * NB * 1568];     // layer2 spikes (A of fc1, bf16)
__device__ float g_U3 [T_SIM * NB * 410];              // fc1 out -> spikes (in place)
__device__ float g_U4 [T_SIM * NB * 10];               // fc2 out
__device__ float g_W1R[400];                            // w1 reordered [kq][oc]
__device__ u16   g_W2L[25 * 3 * 32 * 16];               // w2 bf16 limbs [kq][limb][oc][ci]
__device__ u16   g_WF1L[3 * 448 * 1568];                // wf1 bf16 limbs [l][n(pad448)][k]

// ---------------- encode: bernoulli spikes, smem tile transpose ----------------
__global__ void k_encode(const float* __restrict__ rand_u, const float* __restrict__ img) {
    __shared__ float tile[32][101];
    __shared__ float imgs[32];
    int bp0 = blockIdx.x * 32;
    int tid = threadIdx.x;                 // 256
    if (tid < 32) imgs[tid] = img[bp0 + tid];
    for (int idx = tid; idx < 3200; idx += 256) {
        int bl = idx / 100, t = idx - bl * 100;
        tile[bl][t] = rand_u[(bp0 + bl) * 100 + t];
    }
    __syncthreads();
    for (int idx = tid; idx < 3200; idx += 256) {
        int t = idx >> 5, bl = idx & 31;
        g_S0[t * 25088 + bp0 + bl] = (tile[bl][t] < imgs[bl]) ? 1.0f : 0.0f;
    }
}

// ---- exact 3-limb bf16 split helper ------------------------------------------
__device__ __forceinline__ u16 limb_of(float w, int l) {
    u32 u0 = __float_as_uint(w);
    float h1 = __uint_as_float(u0 & 0xFFFF0000u);
    float r1 = w - h1;                       // exact
    u32 u1 = __float_as_uint(r1);
    float h2 = __uint_as_float(u1 & 0xFFFF0000u);
    float r2 = r1 - h2;                      // exact, <=8 significant bits
    u32 u2r = __float_as_uint(r2);
    return (l == 0) ? (u16)(u0 >> 16) : (l == 1) ? (u16)(u1 >> 16) : (u16)(u2r >> 16);
}

// ------- weight prep: w1 reorder + w2 limbs + wf1 limbs ------------------------
__global__ void k_prep_w(const float* __restrict__ w1, const float* __restrict__ w2,
                         const float* __restrict__ wf1) {
    int i = blockIdx.x * blockDim.x + threadIdx.x;
    if (i < 400) {
        int oc = i & 15, kq = i >> 4;
        g_W1R[i] = w1[oc * 25 + kq];
    }
    if (i < 38400) {   // [kq][l][oc][ci]
        int ci = i & 15;
        int oc = (i >> 4) & 31;
        int l  = (i >> 9) % 3;
        int kq = i / 1536;
        g_W2L[i] = limb_of(w2[oc * 400 + ci * 25 + kq], l);
    }
    if (i < 3 * 448 * 1568) {  // layout (l*448+n)*1568+k == i
        int l = i / (448 * 1568);
        int r = i - l * (448 * 1568);
        int n = r / 1568, k = r - n * 1568;
        float w = (n < 410) ? wf1[n * 1568 + k] : 0.f;
        g_WF1L[i] = limb_of(w, l);
    }
}

// ---------------- psp value scan (no spike), in place: S0 -> P0 ----------------
__global__ void k_psp_ns(float* __restrict__ u, int plane) {
    int i = blockIdx.x * blockDim.x + threadIdx.x;
    if (i >= plane) return;
    float* p = u + i;
    float s1 = 0.f, s2 = 0.f;
    #pragma unroll 4
    for (int t = 0; t < T_SIM; t++) {
        float x = p[(size_t)t * plane];
        s2 = R_DEC * (s2 + s1);
        s1 = R_DEC * s1 + x;
        p[(size_t)t * plane] = C_EPS * s2;
    }
}

// ---- conv1 on P0: 1->16ch 28x28 5x5 pad2, epilogue spike + 2x2 pool(x1.1) -----
__global__ void k_conv1() {
    __shared__ float in_s[32 * 32];
    __shared__ float w_s[400];
    __shared__ __nv_bfloat16 spk[16 * 784];      // 25088 B, spikes full-res
    int tb = blockIdx.x; int t = tb >> 5, b = tb & 31;
    int tid = threadIdx.x;            // 448 threads
    for (int i = tid; i < 1024; i += blockDim.x) in_s[i] = 0.f;
    __syncthreads();
    const float* src = &g_S0[t * (NB * 784) + b * 784];
    for (int i = tid; i < 784; i += blockDim.x) {
        int y = i / 28, x = i - y * 28;
        in_s[(y + 2) * 32 + (x + 2)] = src[i];
    }
    for (int i = tid; i < 400; i += blockDim.x) w_s[i] = g_W1R[i];
    __syncthreads();

    int ocg = tid / 112; int rem = tid % 112;
    int y = rem >> 2; int x0 = (rem & 3) * 7;
    float acc[4][7];
    #pragma unroll
    for (int o = 0; o < 4; o++)
        #pragma unroll
        for (int xx = 0; xx < 7; xx++) acc[o][xx] = 0.f;

    #pragma unroll
    for (int ky = 0; ky < 5; ky++) {
        float rin[11];
        #pragma unroll
        for (int j = 0; j < 11; j++) rin[j] = in_s[(y + ky) * 32 + x0 + j];
        #pragma unroll
        for (int kx = 0; kx < 5; kx++) {
            float4 w = *(const float4*)&w_s[(ky * 5 + kx) * 16 + ocg * 4];
            #pragma unroll
            for (int xx = 0; xx < 7; xx++) {
                float v = rin[kx + xx];
                acc[0][xx] += w.x * v; acc[1][xx] += w.y * v;
                acc[2][xx] += w.z * v; acc[3][xx] += w.w * v;
            }
        }
    }
    // spike -> smem
    #pragma unroll
    for (int o = 0; o < 4; o++)
        #pragma unroll
        for (int xx = 0; xx < 7; xx++)
            spk[(ocg * 4 + o) * 784 + y * 28 + x0 + xx] =
                (acc[o][xx] >= 1.0f) ? (__nv_bfloat16)1.0f : (__nv_bfloat16)0.0f;
    __syncthreads();
    // 2x2 pool of spikes (pre-psp), write pooled plane [16][14][14]
    float* dstp = &g_U1[(size_t)t * (NB * 3136) + b * 3136];
    for (int i = tid; i < 3136; i += blockDim.x) {
        int c = i / 196, r = i - c * 196;
        int py = r / 14, px = r - py * 14;
        int base = c * 784 + (2 * py) * 28 + 2 * px;
        float s = (float)spk[base] + (float)spk[base + 1]
                + (float)spk[base + 28] + (float)spk[base + 29];
        dstp[i] = 1.1f * s;
    }
}

// ---------------- psp + spike scan -> bf16 out ----------------------------------
__global__ void k_psp_spike_b(const float* __restrict__ u, __nv_bfloat16* __restrict__ sout,
                              int plane) {
    int i = blockIdx.x * blockDim.x + threadIdx.x;
    if (i >= plane) return;
    float s1 = 0.f, s2 = 0.f;
    #pragma unroll 4
    for (int t = 0; t < T_SIM; t++) {
        float x = u[(size_t)t * plane + i];
        s2 = R_DEC * (s2 + s1);
        s1 = R_DEC * s1 + x;
        sout[(size_t)t * plane + i] = (C_EPS * s2 >= 1.0f) ? (__nv_bfloat16)1.0f
                                                           : (__nv_bfloat16)0.0f;
    }
}

// ------- fused: psp+spike (full res) -> 2x2 pool(x1.1) -> psp+spike ------------
template <typename TOut>
__global__ void k_fused_pp(const float* __restrict__ uin, TOut* __restrict__ sout,
                           int Hin, int planeIn, int planeOut, int total) {
    int i = blockIdx.x * blockDim.x + threadIdx.x;
    if (i >= total) return;
    int ho = Hin >> 1;
    int x  = i % ho;
    int y  = (i / ho) % ho;
    int bc = i / (ho * ho);
    const float* base = uin + bc * Hin * Hin + (2 * y) * Hin + 2 * x;

    float a1 = 0.f, a2 = 0.f, b1 = 0.f, b2 = 0.f;
    float c1 = 0.f, c2 = 0.f, d1 = 0.f, d2 = 0.f;
    float o1 = 0.f, o2 = 0.f;

    #pragma unroll 4
    for (int t = 0; t < T_SIM; t++) {
        float2 top = *(const float2*)(base + (size_t)t * planeIn);
        float2 bot = *(const float2*)(base + (size_t)t * planeIn + Hin);

        a2 = R_DEC * (a2 + a1); a1 = R_DEC * a1 + top.x;
        b2 = R_DEC * (b2 + b1); b1 = R_DEC * b1 + top.y;
        c2 = R_DEC * (c2 + c1); c1 = R_DEC * c1 + bot.x;
        d2 = R_DEC * (d2 + d1); d1 = R_DEC * d1 + bot.y;

        float spkA = (C_EPS * a2 >= 1.0f) ? 1.0f : 0.0f;
        float spkB = (C_EPS * b2 >= 1.0f) ? 1.0f : 0.0f;
        float spkC = (C_EPS * c2 >= 1.0f) ? 1.0f : 0.0f;
        float spkD = (C_EPS * d2 >= 1.0f) ? 1.0f : 0.0f;
        float pool = 1.1f * ((spkA + spkB) + (spkC + spkD));

        o2 = R_DEC * (o2 + o1); o1 = R_DEC * o1 + pool;
        sout[(size_t)t * planeOut + i] = (TOut)((C_EPS * o2 >= 1.0f) ? 1.0f : 0.0f);
    }
}

// ---------------- generic psp + spike (in place, fp32) -------------------------
__global__ void k_psp(float* __restrict__ u, int plane) {
    int i = blockIdx.x * blockDim.x + threadIdx.x;
    if (i >= plane) return;
    float* p = u + i;
    float s1 = 0.f, s2 = 0.f;
    #pragma unroll 4
    for (int t = 0; t < T_SIM; t++) {
        float x = p[(size_t)t * plane];
        s2 = R_DEC * (s2 + s1);
        s1 = R_DEC * s1 + x;
        p[(size_t)t * plane] = (C_EPS * s2 >= 1.0f) ? 1.0f : 0.0f;
    }
}

// ---- mma.m16n8k16 bf16 helper ---------------------------------------------------
__device__ __forceinline__ void mma16816(float* c, const u32* a, u32 b0, u32 b1) {
    asm volatile(
        "mma.sync.aligned.m16n8k16.row.col.f32.bf16.bf16.f32 "
        "{%0,%1,%2,%3}, {%4,%5,%6,%7}, {%8,%9}, {%0,%1,%2,%3};"
        : "+f"(c[0]), "+f"(c[1]), "+f"(c[2]), "+f"(c[3])
        : "r"(a[0]), "r"(a[1]), "r"(a[2]), "r"(a[3]), "r"(b0), "r"(b1));
}

// ---- conv2 via tensor cores (unchanged from R7, exact 3-limb) -------------------
__global__ __launch_bounds__(256) void k_conv2_mma() {
    __shared__ __nv_bfloat16 in_s[18 * 24 * 16];   // [row][col][ci]
    int tb = blockIdx.x; int t = tb >> 5, b = tb & 31;
    int tid = threadIdx.x, warp = tid >> 5, lane = tid & 31;

    u32* z = (u32*)in_s;
    for (int i = tid; i < 3456; i += 256) z[i] = 0u;
    __syncthreads();
    const __nv_bfloat16* src = g_S1p + (size_t)t * (NB * 3136) + b * 3136;
    for (int i = tid; i < 3136; i += 256) {
        int ci = i / 196, p = i - ci * 196;
        int y = p / 14, x = p - y * 14;
        in_s[((y + 2) * 24 + (x + 2)) * 16 + ci] = src[i];
    }
    __syncthreads();

    int g  = lane >> 2;
    int tq = lane & 3;
    int m  = warp >> 2;
    int nr0 = (warp & 3) * 7;

    float acc[7][4];
    #pragma unroll
    for (int j = 0; j < 7; j++)
        #pragma unroll
        for (int q = 0; q < 4; q++) acc[j][q] = 0.f;

    const u32* wl = (const u32*)g_W2L;

    for (int kq = 0; kq < 25; kq++) {
        int ky = kq / 5, kx = kq - ky * 5;
        u32 af[3][4];
        #pragma unroll
        for (int l = 0; l < 3; l++) {
            int base = ((kq * 3 + l) * 32 + m * 16 + g) * 8;
            af[l][0] = __ldg(&wl[base + tq]);
            af[l][1] = __ldg(&wl[base + 64 + tq]);
            af[l][2] = __ldg(&wl[base + tq + 4]);
            af[l][3] = __ldg(&wl[base + 64 + tq + 4]);
        }
        #pragma unroll
        for (int j = 0; j < 7; j++) {
            int nr = nr0 + j;
            int y = nr >> 1, xh = (nr & 1) * 8;
            const u32* bp = (const u32*)&in_s[((y + ky) * 24 + (xh + g + kx)) * 16 + tq * 2];
            u32 b0 = bp[0];
            u32 b1 = bp[4];
            mma16816(acc[j], af[0], b0, b1);
            mma16816(acc[j], af[1], b0, b1);
            mma16816(acc[j], af[2], b0, b1);
        }
    }

    float* dst = g_U2 + (size_t)t * (NB * 6272) + b * 6272;
    int oc0 = m * 16 + g;
    int xp0 = tq * 2;
    #pragma unroll
    for (int j = 0; j < 7; j++) {
        int nr = nr0 + j;
        int y = nr >> 1, xh = (nr & 1) * 8;
        int xp = xh + xp0;
        if (xp <= 12) {
            float2 v0; v0.x = acc[j][0]; v0.y = acc[j][1];
            float2 v1; v1.x = acc[j][2]; v1.y = acc[j][3];
            *(float2*)&dst[oc0 * 196 + y * 14 + xp] = v0;
            *(float2*)&dst[(oc0 + 8) * 196 + y * 14 + xp] = v1;
        }
    }
}

// ---- fc1 via tensor cores: C[3200x410] = S2p(bf16 spikes) x wf1^T (3 limbs) ----
// block tile 64(M)x64(N), 8 warps (2Mx4N), warp tile 32x16; K chunks of 32.
__global__ __launch_bounds__(256) void k_dense1_mma() {
    __shared__ __nv_bfloat16 As[64 * 40];        // row pad 40 bf16 (20 u32)
    __shared__ __nv_bfloat16 Bs[3 * 64 * 40];
    int m0 = blockIdx.y * 64, n0 = blockIdx.x * 64;
    int tid = threadIdx.x, warp = tid >> 5, lane = tid & 31;
    int g = lane >> 2, tq = lane & 3;
    int wm = warp >> 2, wn = warp & 3;
    u32* as32 = (u32*)As;
    u32* bs32 = (u32*)Bs;
    const u32* a_src = (const u32*)g_S2p;        // row stride 784 u32
    const u32* b_src = (const u32*)g_WF1L;       // row stride 784 u32

    float acc[2][2][4];
    #pragma unroll
    for (int mt = 0; mt < 2; mt++)
        #pragma unroll
        for (int nt = 0; nt < 2; nt++)
            #pragma unroll
            for (int q = 0; q < 4; q++) acc[mt][nt][q] = 0.f;

    int arow = tid >> 2, ac = (tid & 3) * 4;     // 64 rows x 4 u32 each

    for (int kc = 0; kc < 784; kc += 16) {       // 16 u32 = 32 bf16 per chunk
        uint4 av = *(const uint4*)&a_src[(size_t)(m0 + arow) * 784 + kc + ac];
        *(uint4*)&as32[arow * 20 + ac] = av;
        #pragma unroll
        for (int l = 0; l < 3; l++) {
            uint4 bv = *(const uint4*)&b_src[(size_t)(l * 448 + n0 + arow) * 784 + kc + ac];
            *(uint4*)&bs32[(l * 64 + arow) * 20 + ac] = bv;
        }
        __syncthreads();
        #pragma unroll
        for (int ks = 0; ks < 2; ks++) {
            int ko = ks * 8;
            u32 a[2][4];
            #pragma unroll
            for (int mt = 0; mt < 2; mt++) {
                int r = wm * 32 + mt * 16 + g;
                a[mt][0] = as32[r * 20 + ko + tq];
                a[mt][1] = as32[(r + 8) * 20 + ko + tq];
                a[mt][2] = as32[r * 20 + ko + tq + 4];
                a[mt][3] = as32[(r + 8) * 20 + ko + tq + 4];
            }
            #pragma unroll
            for (int l = 0; l < 3; l++)
                #pragma unroll
                for (int nt = 0; nt < 2; nt++) {
                    int ccol = l * 64 + wn * 16 + nt * 8 + g;
                    u32 b0 = bs32[ccol * 20 + ko + tq];
                    u32 b1 = bs32[ccol * 20 + ko + tq + 4];
                    mma16816(acc[0][nt], a[0], b0, b1);
                    mma16816(acc[1][nt], a[1], b0, b1);
                }
        }
        __syncthreads();
    }

    #pragma unroll
    for (int mt = 0; mt < 2; mt++)
        #pragma unroll
        for (int nt = 0; nt < 2; nt++) {
            int mrow = m0 + wm * 32 + mt * 16 + g;
            int n = n0 + wn * 16 + nt * 8 + tq * 2;
            if (n < 410) {
                g_U3[mrow * 410 + n] = acc[mt][nt][0];
                g_U3[(mrow + 8) * 410 + n] = acc[mt][nt][2];
            }
            if (n + 1 < 410) {
                g_U3[mrow * 410 + n + 1] = acc[mt][nt][1];
                g_U3[(mrow + 8) * 410 + n + 1] = acc[mt][nt][3];
            }
        }
}

// ---------------- fc2: [3200,10] = S3[3200,410] * wf2^T ------------------------
__global__ void k_dense2(const float* __restrict__ wf2) {
    int i = blockIdx.x * blockDim.x + threadIdx.x;
    if (i >= 32000) return;
    int m = i / 10, o = i - (i / 10) * 10;
    const float* a = &g_U3[m * 410];
    const float* w = &wf2[o * 410];
    float acc = 0.f;
    #pragma unroll 2
    for (int k = 0; k < 410; k++) acc += a[k] * w[k];
    g_U4[m * 10 + o] = acc;
}

// ---------------- final psp + spike + transpose to [b][o][t] -------------------
__global__ void k_final(float* __restrict__ out) {
    int i = threadIdx.x;                   // 320 = b*10+o
    if (i >= 320) return;
    float s1 = 0.f, s2 = 0.f;
    #pragma unroll 4
    for (int t = 0; t < T_SIM; t++) {
        float x = g_U4[t * 320 + i];
        s2 = R_DEC * (s2 + s1);
        s1 = R_DEC * s1 + x;
        out[i * T_SIM + t] = (C_EPS * s2 >= 1.0f) ? 1.0f : 0.0f;
    }
}

// -------------------------------------------------------------------------------
extern "C" void kernel_launch(void* const* d_in, const int* in_sizes, int n_in,
                              void* d_out, int out_size) {
    const float* img    = (const float*)d_in[0];
    const float* rand_u = (const float*)d_in[1];
    const float* w1     = (const float*)d_in[2];
    const float* w2     = (const float*)d_in[3];
    const float* wf1    = (const float*)d_in[4];
    const float* wf2    = (const float*)d_in[5];
    float* out = (float*)d_out;

    void *pS0, *pU1, *pU2, *pU3, *pS1p, *pS2p;
    cudaGetSymbolAddress(&pS0,  g_S0);
    cudaGetSymbolAddress(&pU1,  g_U1);
    cudaGetSymbolAddress(&pU2,  g_U2);
    cudaGetSymbolAddress(&pU3,  g_U3);
    cudaGetSymbolAddress(&pS1p, g_S1p);
    cudaGetSymbolAddress(&pS2p, g_S2p);

    k_encode<<<784, 256>>>(rand_u, img);
    k_prep_w<<<8232, 256>>>(w1, w2, wf1);

    // layer 1: psp first (linear commute), conv1 with spike+pool epilogue
    k_psp_ns<<<98, 256>>>((float*)pS0, NB * 784);
    k_conv1<<<3200, 448>>>();
    k_psp_spike_b<<<392, 256>>>((const float*)pU1, (__nv_bfloat16*)pS1p, NB * 16 * 196);

    // layer 2: tensor-core conv on spikes, then fused psp/pool chain -> bf16
    k_conv2_mma<<<3200, 256>>>();
    k_fused_pp<__nv_bfloat16><<<196, 256>>>((const float*)pU2, (__nv_bfloat16*)pS2p,
                             14, NB * 32 * 196, NB * 1568, NB * 1568);

    // fc1 on tensor cores (exact 3-limb), then scan
    dim3 g1(7, 50);
    k_dense1_mma<<<g1, 256>>>();
    k_psp<<<52, 256>>>((float*)pU3, NB * 410);

    k_dense2<<<125, 256>>>(wf2);
    k_final<<<1, 320>>>(out);
}

// round 14
// speedup vs baseline: 1.9221x; 1.1481x over previous
#include <cuda_runtime.h>
#include <cuda_bf16.h>

#define T_SIM 100
#define NB 32
// e^{-1/tau}, tau = 10
#define R_DEC 0.9048374180359595f
// e/tau
#define C_EPS 0.2718281828459045f

typedef unsigned int u32;
typedef unsigned short u16;

// ---------------- scratch (device globals; no allocation allowed) -------------
__device__ float g_S0 [T_SIM * NB * 784];              // psp(encode spikes), time-major
__device__ float g_U1 [T_SIM * NB * 16 * 196];         // pooled pre-psp (layer1)
__device__ __nv_bfloat16 g_S1p[T_SIM * NB * 16 * 196]; // layer1 spikes (bf16 exact)
__device__ float g_U2 [T_SIM * NB * 32 * 196];         // conv2 raw membrane input
__device__ __nv_bfloat16 g_S2p[T_SIM * NB * 1568];     // layer2 spikes (A of fc1, bf16)
__device__ float g_U3 [T_SIM * NB * 410];              // fc1 out -> spikes (in place)
__device__ float g_U4 [T_SIM * NB * 10];               // fc2 out
__device__ float g_W1R[400];                            // w1 reordered [kq][oc]
__device__ u16   g_W2L[25 * 3 * 32 * 16];               // w2 bf16 limbs [kq][limb][oc][ci]
__device__ u16   g_WF1L[3 * 448 * 1568];                // wf1 bf16 limbs [l][n(pad448)][k]

// ------- encode: bernoulli spikes + fused psp value scan, smem transpose -------
__global__ void k_encode_psp(const float* __restrict__ rand_u, const float* __restrict__ img) {
    __shared__ float tile[32][101];
    __shared__ float imgs[32];
    int bp0 = blockIdx.x * 32;
    int tid = threadIdx.x;                 // 256
    if (tid < 32) imgs[tid] = img[bp0 + tid];
    for (int idx = tid; idx < 3200; idx += 256) {
        int bl = idx / 100, t = idx - bl * 100;
        tile[bl][t] = rand_u[(bp0 + bl) * 100 + t];
    }
    __syncthreads();
    if (tid < 32) {                        // in-smem temporal scan (psp, no spike)
        float s1 = 0.f, s2 = 0.f, im = imgs[tid];
        #pragma unroll 4
        for (int t = 0; t < T_SIM; t++) {
            float x = (tile[tid][t] < im) ? 1.0f : 0.0f;
            s2 = R_DEC * (s2 + s1);
            s1 = R_DEC * s1 + x;
            tile[tid][t] = C_EPS * s2;
        }
    }
    __syncthreads();
    for (int idx = tid; idx < 3200; idx += 256) {
        int t = idx >> 5, bl = idx & 31;
        g_S0[t * 25088 + bp0 + bl] = tile[bl][t];   // coalesced
    }
}

// ---- exact 3-limb bf16 split helper ------------------------------------------
__device__ __forceinline__ u16 limb_of(float w, int l) {
    u32 u0 = __float_as_uint(w);
    float h1 = __uint_as_float(u0 & 0xFFFF0000u);
    float r1 = w - h1;                       // exact
    u32 u1 = __float_as_uint(r1);
    float h2 = __uint_as_float(u1 & 0xFFFF0000u);
    float r2 = r1 - h2;                      // exact, <=8 significant bits
    u32 u2r = __float_as_uint(r2);
    return (l == 0) ? (u16)(u0 >> 16) : (l == 1) ? (u16)(u1 >> 16) : (u16)(u2r >> 16);
}

// ------- weight prep: w1 reorder + w2 limbs + wf1 limbs ------------------------
__global__ void k_prep_w(const float* __restrict__ w1, const float* __restrict__ w2,
                         const float* __restrict__ wf1) {
    int i = blockIdx.x * blockDim.x + threadIdx.x;
    if (i < 400) {
        int oc = i & 15, kq = i >> 4;
        g_W1R[i] = w1[oc * 25 + kq];
    }
    if (i < 38400) {   // [kq][l][oc][ci]
        int ci = i & 15;
        int oc = (i >> 4) & 31;
        int l  = (i >> 9) % 3;
        int kq = i / 1536;
        g_W2L[i] = limb_of(w2[oc * 400 + ci * 25 + kq], l);
    }
    if (i < 3 * 448 * 1568) {  // layout (l*448+n)*1568+k == i
        int l = i / (448 * 1568);
        int r = i - l * (448 * 1568);
        int n = r / 1568, k = r - n * 1568;
        float w = (n < 410) ? wf1[n * 1568 + k] : 0.f;
        g_WF1L[i] = limb_of(w, l);
    }
}

// ---- conv1 on P0: 1->16ch 28x28 5x5 pad2; spike + 2x2 pool fully in registers --
// 448 threads: oc = tid/28 (16), rem = tid%28 -> py (14) x xh (2).
// Each thread: conv for raw rows {2py,2py+1} x 14 raw cols -> spike -> pool -> 7 out.
__global__ __launch_bounds__(448) void k_conv1() {
    __shared__ float in_s[32 * 33];   // rows padded to 33 floats (bank-conflict fix)
    __shared__ float w_s[400];        // [kq][oc]
    int tb = blockIdx.x; int t = tb >> 5, b = tb & 31;
    int tid = threadIdx.x;
    for (int i = tid; i < 1056; i += 448) in_s[i] = 0.f;
    __syncthreads();
    const float* src = &g_S0[t * (NB * 784) + b * 784];
    for (int i = tid; i < 784; i += 448) {
        int y = i / 28, x = i - y * 28;
        in_s[(y + 2) * 33 + (x + 2)] = src[i];
    }
    for (int i = tid; i < 400; i += 448) w_s[i] = g_W1R[i];
    __syncthreads();

    int oc  = tid / 28;
    int rem = tid - oc * 28;
    int py  = rem >> 1;
    int xh  = rem & 1;
    int xb  = xh * 14;                // raw x base (also +2 halo handled by layout)

    float acc0[14], acc1[14];
    #pragma unroll
    for (int x = 0; x < 14; x++) { acc0[x] = 0.f; acc1[x] = 0.f; }

    #pragma unroll
    for (int r6 = 0; r6 < 6; r6++) {
        // input raw row = 2py - 2 + r6  ->  smem row index = 2py + r6
        float rin[18];
        #pragma unroll
        for (int j = 0; j < 18; j++) rin[j] = in_s[(2 * py + r6) * 33 + xb + j];
        if (r6 <= 4) {                // contributes to out row 2py with ky = r6
            #pragma unroll
            for (int kx = 0; kx < 5; kx++) {
                float w = w_s[(r6 * 5 + kx) * 16 + oc];
                #pragma unroll
                for (int x = 0; x < 14; x++) acc0[x] += w * rin[x + kx];
            }
        }
        if (r6 >= 1) {                // contributes to out row 2py+1 with ky = r6-1
            #pragma unroll
            for (int kx = 0; kx < 5; kx++) {
                float w = w_s[((r6 - 1) * 5 + kx) * 16 + oc];
                #pragma unroll
                for (int x = 0; x < 14; x++) acc1[x] += w * rin[x + kx];
            }
        }
    }

    // spike + 2x2 pool in registers, write 7 pooled floats (contiguous per group)
    float* dstp = &g_U1[(size_t)t * (NB * 3136) + b * 3136 + oc * 196 + py * 14 + xh * 7];
    #pragma unroll
    for (int xp = 0; xp < 7; xp++) {
        float s = ((acc0[2 * xp] >= 1.0f) ? 1.0f : 0.0f)
                + ((acc0[2 * xp + 1] >= 1.0f) ? 1.0f : 0.0f)
                + ((acc1[2 * xp] >= 1.0f) ? 1.0f : 0.0f)
                + ((acc1[2 * xp + 1] >= 1.0f) ? 1.0f : 0.0f);
        dstp[xp] = 1.1f * s;
    }
}

// ---------------- psp + spike scan -> bf16 out ----------------------------------
__global__ void k_psp_spike_b(const float* __restrict__ u, __nv_bfloat16* __restrict__ sout,
                              int plane) {
    int i = blockIdx.x * blockDim.x + threadIdx.x;
    if (i >= plane) return;
    float s1 = 0.f, s2 = 0.f;
    #pragma unroll 4
    for (int t = 0; t < T_SIM; t++) {
        float x = u[(size_t)t * plane + i];
        s2 = R_DEC * (s2 + s1);
        s1 = R_DEC * s1 + x;
        sout[(size_t)t * plane + i] = (C_EPS * s2 >= 1.0f) ? (__nv_bfloat16)1.0f
                                                           : (__nv_bfloat16)0.0f;
    }
}

// ------- fused: psp+spike (full res) -> 2x2 pool(x1.1) -> psp+spike ------------
template <typename TOut>
__global__ void k_fused_pp(const float* __restrict__ uin, TOut* __restrict__ sout,
                           int Hin, int planeIn, int planeOut, int total) {
    int i = blockIdx.x * blockDim.x + threadIdx.x;
    if (i >= total) return;
    int ho = Hin >> 1;
    int x  = i % ho;
    int y  = (i / ho) % ho;
    int bc = i / (ho * ho);
    const float* base = uin + bc * Hin * Hin + (2 * y) * Hin + 2 * x;

    float a1 = 0.f, a2 = 0.f, b1 = 0.f, b2 = 0.f;
    float c1 = 0.f, c2 = 0.f, d1 = 0.f, d2 = 0.f;
    float o1 = 0.f, o2 = 0.f;

    #pragma unroll 4
    for (int t = 0; t < T_SIM; t++) {
        float2 top = *(const float2*)(base + (size_t)t * planeIn);
        float2 bot = *(const float2*)(base + (size_t)t * planeIn + Hin);

        a2 = R_DEC * (a2 + a1); a1 = R_DEC * a1 + top.x;
        b2 = R_DEC * (b2 + b1); b1 = R_DEC * b1 + top.y;
        c2 = R_DEC * (c2 + c1); c1 = R_DEC * c1 + bot.x;
        d2 = R_DEC * (d2 + d1); d1 = R_DEC * d1 + bot.y;

        float spkA = (C_EPS * a2 >= 1.0f) ? 1.0f : 0.0f;
        float spkB = (C_EPS * b2 >= 1.0f) ? 1.0f : 0.0f;
        float spkC = (C_EPS * c2 >= 1.0f) ? 1.0f : 0.0f;
        float spkD = (C_EPS * d2 >= 1.0f) ? 1.0f : 0.0f;
        float pool = 1.1f * ((spkA + spkB) + (spkC + spkD));

        o2 = R_DEC * (o2 + o1); o1 = R_DEC * o1 + pool;
        sout[(size_t)t * planeOut + i] = (TOut)((C_EPS * o2 >= 1.0f) ? 1.0f : 0.0f);
    }
}

// ---------------- generic psp + spike (in place, fp32) -------------------------
__global__ void k_psp(float* __restrict__ u, int plane) {
    int i = blockIdx.x * blockDim.x + threadIdx.x;
    if (i >= plane) return;
    float* p = u + i;
    float s1 = 0.f, s2 = 0.f;
    #pragma unroll 4
    for (int t = 0; t < T_SIM; t++) {
        float x = p[(size_t)t * plane];
        s2 = R_DEC * (s2 + s1);
        s1 = R_DEC * s1 + x;
        p[(size_t)t * plane] = (C_EPS * s2 >= 1.0f) ? 1.0f : 0.0f;
    }
}

// ---- mma.m16n8k16 bf16 helper ---------------------------------------------------
__device__ __forceinline__ void mma16816(float* c, const u32* a, u32 b0, u32 b1) {
    asm volatile(
        "mma.sync.aligned.m16n8k16.row.col.f32.bf16.bf16.f32 "
        "{%0,%1,%2,%3}, {%4,%5,%6,%7}, {%8,%9}, {%0,%1,%2,%3};"
        : "+f"(c[0]), "+f"(c[1]), "+f"(c[2]), "+f"(c[3])
        : "r"(a[0]), "r"(a[1]), "r"(a[2]), "r"(a[3]), "r"(b0), "r"(b1));
}

// ---- conv2 via tensor cores (exact 3-limb) --------------------------------------
__global__ __launch_bounds__(256) void k_conv2_mma() {
    __shared__ __nv_bfloat16 in_s[18 * 24 * 16];   // [row][col][ci]
    int tb = blockIdx.x; int t = tb >> 5, b = tb & 31;
    int tid = threadIdx.x, warp = tid >> 5, lane = tid & 31;

    u32* z = (u32*)in_s;
    for (int i = tid; i < 3456; i += 256) z[i] = 0u;
    __syncthreads();
    const __nv_bfloat16* src = g_S1p + (size_t)t * (NB * 3136) + b * 3136;
    for (int i = tid; i < 3136; i += 256) {
        int ci = i / 196, p = i - ci * 196;
        int y = p / 14, x = p - y * 14;
        in_s[((y + 2) * 24 + (x + 2)) * 16 + ci] = src[i];
    }
    __syncthreads();

    int g  = lane >> 2;
    int tq = lane & 3;
    int m  = warp >> 2;
    int nr0 = (warp & 3) * 7;

    float acc[7][4];
    #pragma unroll
    for (int j = 0; j < 7; j++)
        #pragma unroll
        for (int q = 0; q < 4; q++) acc[j][q] = 0.f;

    const u32* wl = (const u32*)g_W2L;

    for (int kq = 0; kq < 25; kq++) {
        int ky = kq / 5, kx = kq - ky * 5;
        u32 af[3][4];
        #pragma unroll
        for (int l = 0; l < 3; l++) {
            int base = ((kq * 3 + l) * 32 + m * 16 + g) * 8;
            af[l][0] = __ldg(&wl[base + tq]);
            af[l][1] = __ldg(&wl[base + 64 + tq]);
            af[l][2] = __ldg(&wl[base + tq + 4]);
            af[l][3] = __ldg(&wl[base + 64 + tq + 4]);
        }
        #pragma unroll
        for (int j = 0; j < 7; j++) {
            int nr = nr0 + j;
            int y = nr >> 1, xh = (nr & 1) * 8;
            const u32* bp = (const u32*)&in_s[((y + ky) * 24 + (xh + g + kx)) * 16 + tq * 2];
            u32 b0 = bp[0];
            u32 b1 = bp[4];
            mma16816(acc[j], af[0], b0, b1);
            mma16816(acc[j], af[1], b0, b1);
            mma16816(acc[j], af[2], b0, b1);
        }
    }

    float* dst = g_U2 + (size_t)t * (NB * 6272) + b * 6272;
    int oc0 = m * 16 + g;
    int xp0 = tq * 2;
    #pragma unroll
    for (int j = 0; j < 7; j++) {
        int nr = nr0 + j;
        int y = nr >> 1, xh = (nr & 1) * 8;
        int xp = xh + xp0;
        if (xp <= 12) {
            float2 v0; v0.x = acc[j][0]; v0.y = acc[j][1];
            float2 v1; v1.x = acc[j][2]; v1.y = acc[j][3];
            *(float2*)&dst[oc0 * 196 + y * 14 + xp] = v0;
            *(float2*)&dst[(oc0 + 8) * 196 + y * 14 + xp] = v1;
        }
    }
}

// ---- fc1 via tensor cores: C[3200x410] = S2p(bf16 spikes) x wf1^T (3 limbs) ----
__global__ __launch_bounds__(256) void k_dense1_mma() {
    __shared__ __nv_bfloat16 As[64 * 40];        // row pad 40 bf16 (20 u32)
    __shared__ __nv_bfloat16 Bs[3 * 64 * 40];
    int m0 = blockIdx.y * 64, n0 = blockIdx.x * 64;
    int tid = threadIdx.x, warp = tid >> 5, lane = tid & 31;
    int g = lane >> 2, tq = lane & 3;
    int wm = warp >> 2, wn = warp & 3;
    u32* as32 = (u32*)As;
    u32* bs32 = (u32*)Bs;
    const u32* a_src = (const u32*)g_S2p;        // row stride 784 u32
    const u32* b_src = (const u32*)g_WF1L;       // row stride 784 u32

    float acc[2][2][4];
    #pragma unroll
    for (int mt = 0; mt < 2; mt++)
        #pragma unroll
        for (int nt = 0; nt < 2; nt++)
            #pragma unroll
            for (int q = 0; q < 4; q++) acc[mt][nt][q] = 0.f;

    int arow = tid >> 2, ac = (tid & 3) * 4;     // 64 rows x 4 u32 each

    for (int kc = 0; kc < 784; kc += 16) {       // 16 u32 = 32 bf16 per chunk
        uint4 av = *(const uint4*)&a_src[(size_t)(m0 + arow) * 784 + kc + ac];
        *(uint4*)&as32[arow * 20 + ac] = av;
        #pragma unroll
        for (int l = 0; l < 3; l++) {
            uint4 bv = *(const uint4*)&b_src[(size_t)(l * 448 + n0 + arow) * 784 + kc + ac];
            *(uint4*)&bs32[(l * 64 + arow) * 20 + ac] = bv;
        }
        __syncthreads();
        #pragma unroll
        for (int ks = 0; ks < 2; ks++) {
            int ko = ks * 8;
            u32 a[2][4];
            #pragma unroll
            for (int mt = 0; mt < 2; mt++) {
                int r = wm * 32 + mt * 16 + g;
                a[mt][0] = as32[r * 20 + ko + tq];
                a[mt][1] = as32[(r + 8) * 20 + ko + tq];
                a[mt][2] = as32[r * 20 + ko + tq + 4];
                a[mt][3] = as32[(r + 8) * 20 + ko + tq + 4];
            }
            #pragma unroll
            for (int l = 0; l < 3; l++)
                #pragma unroll
                for (int nt = 0; nt < 2; nt++) {
                    int ccol = l * 64 + wn * 16 + nt * 8 + g;
                    u32 b0 = bs32[ccol * 20 + ko + tq];
                    u32 b1 = bs32[ccol * 20 + ko + tq + 4];
                    mma16816(acc[0][nt], a[0], b0, b1);
                    mma16816(acc[1][nt], a[1], b0, b1);
                }
        }
        __syncthreads();
    }

    #pragma unroll
    for (int mt = 0; mt < 2; mt++)
        #pragma unroll
        for (int nt = 0; nt < 2; nt++) {
            int mrow = m0 + wm * 32 + mt * 16 + g;
            int n = n0 + wn * 16 + nt * 8 + tq * 2;
            if (n < 410) {
                g_U3[mrow * 410 + n] = acc[mt][nt][0];
                g_U3[(mrow + 8) * 410 + n] = acc[mt][nt][2];
            }
            if (n + 1 < 410) {
                g_U3[mrow * 410 + n + 1] = acc[mt][nt][1];
                g_U3[(mrow + 8) * 410 + n + 1] = acc[mt][nt][3];
            }
        }
}

// ---------------- fc2: [3200,10] = S3[3200,410] * wf2^T ------------------------
__global__ void k_dense2(const float* __restrict__ wf2) {
    int i = blockIdx.x * blockDim.x + threadIdx.x;
    if (i >= 32000) return;
    int m = i / 10, o = i - (i / 10) * 10;
    const float* a = &g_U3[m * 410];
    const float* w = &wf2[o * 410];
    float acc = 0.f;
    #pragma unroll 2
    for (int k = 0; k < 410; k++) acc += a[k] * w[k];
    g_U4[m * 10 + o] = acc;
}

// ---------------- final psp + spike + transpose to [b][o][t] -------------------
__global__ void k_final(float* __restrict__ out) {
    int i = threadIdx.x;                   // 320 = b*10+o
    if (i >= 320) return;
    float s1 = 0.f, s2 = 0.f;
    #pragma unroll 4
    for (int t = 0; t < T_SIM; t++) {
        float x = g_U4[t * 320 + i];
        s2 = R_DEC * (s2 + s1);
        s1 = R_DEC * s1 + x;
        out[i * T_SIM + t] = (C_EPS * s2 >= 1.0f) ? 1.0f : 0.0f;
    }
}

// -------------------------------------------------------------------------------
extern "C" void kernel_launch(void* const* d_in, const int* in_sizes, int n_in,
                              void* d_out, int out_size) {
    const float* img    = (const float*)d_in[0];
    const float* rand_u = (const float*)d_in[1];
    const float* w1     = (const float*)d_in[2];
    const float* w2     = (const float*)d_in[3];
    const float* wf1    = (const float*)d_in[4];
    const float* wf2    = (const float*)d_in[5];
    float* out = (float*)d_out;

    void *pU1, *pU2, *pU3, *pS1p, *pS2p;
    cudaGetSymbolAddress(&pU1,  g_U1);
    cudaGetSymbolAddress(&pU2,  g_U2);
    cudaGetSymbolAddress(&pU3,  g_U3);
    cudaGetSymbolAddress(&pS1p, g_S1p);
    cudaGetSymbolAddress(&pS2p, g_S2p);

    k_encode_psp<<<784, 256>>>(rand_u, img);     // encode + psp scan fused
    k_prep_w<<<8232, 256>>>(w1, w2, wf1);

    // layer 1: conv1 with spike+pool in registers, then psp+spike -> bf16
    k_conv1<<<3200, 448>>>();
    k_psp_spike_b<<<392, 256>>>((const float*)pU1, (__nv_bfloat16*)pS1p, NB * 16 * 196);

    // layer 2: tensor-core conv on spikes, then fused psp/pool chain -> bf16
    k_conv2_mma<<<3200, 256>>>();
    k_fused_pp<__nv_bfloat16><<<196, 256>>>((const float*)pU2, (__nv_bfloat16*)pS2p,
                             14, NB * 32 * 196, NB * 1568, NB * 1568);

    // fc1 on tensor cores (exact 3-limb), then scan
    dim3 g1(7, 50);
    k_dense1_mma<<<g1, 256>>>();
    k_psp<<<52, 256>>>((float*)pU3, NB * 410);

    k_dense2<<<125, 256>>>(wf2);
    k_final<<<1, 320>>>(out);
}

// round 15
// speedup vs baseline: 1.9830x; 1.0317x over previous
#include <cuda_runtime.h>
#include <cuda_bf16.h>

#define T_SIM 100
#define NB 32
// e^{-1/tau}, tau = 10
#define R_DEC 0.9048374180359595f
// e/tau
#define C_EPS 0.2718281828459045f

typedef unsigned int u32;
typedef unsigned short u16;
typedef unsigned long long u64;

// ---------------- scratch (device globals; no allocation allowed) -------------
__device__ float g_S0 [T_SIM * NB * 784];              // psp(encode spikes), time-major
__device__ float g_U1 [T_SIM * NB * 16 * 196];         // pooled pre-psp (layer1)
__device__ __nv_bfloat16 g_S1p[T_SIM * NB * 16 * 196]; // layer1 spikes (bf16 exact)
__device__ float g_U2 [T_SIM * NB * 32 * 196];         // conv2 raw membrane input
__device__ __nv_bfloat16 g_S2p[T_SIM * NB * 1568];     // layer2 spikes (A of fc1, bf16)
__device__ float g_U3 [T_SIM * NB * 410];              // fc1 out -> spikes (in place)
__device__ float g_U4 [T_SIM * NB * 10];               // fc2 out
__device__ float g_W1R[400];                            // w1 reordered [kq][oc]
__device__ u16   g_W2L[25 * 3 * 32 * 16];               // w2 bf16 limbs [kq][limb][oc][ci]
__device__ u16   g_WF1L[3 * 448 * 1568];                // wf1 bf16 limbs [l][n(pad448)][k]

// ------- encode: bernoulli spikes + fused psp value scan, smem transpose -------
__global__ void k_encode_psp(const float* __restrict__ rand_u, const float* __restrict__ img) {
    __shared__ float tile[32][101];
    __shared__ float imgs[32];
    int bp0 = blockIdx.x * 32;
    int tid = threadIdx.x;                 // 256
    if (tid < 32) imgs[tid] = img[bp0 + tid];
    for (int idx = tid; idx < 3200; idx += 256) {
        int bl = idx / 100, t = idx - bl * 100;
        tile[bl][t] = rand_u[(bp0 + bl) * 100 + t];
    }
    __syncthreads();
    if (tid < 32) {                        // in-smem temporal scan (psp, no spike)
        float s1 = 0.f, s2 = 0.f, im = imgs[tid];
        #pragma unroll 4
        for (int t = 0; t < T_SIM; t++) {
            float x = (tile[tid][t] < im) ? 1.0f : 0.0f;
            s2 = R_DEC * (s2 + s1);
            s1 = R_DEC * s1 + x;
            tile[tid][t] = C_EPS * s2;
        }
    }
    __syncthreads();
    for (int idx = tid; idx < 3200; idx += 256) {
        int t = idx >> 5, bl = idx & 31;
        g_S0[t * 25088 + bp0 + bl] = tile[bl][t];   // coalesced
    }
}

// ---- exact 3-limb bf16 split helpers ------------------------------------------
__device__ __forceinline__ void limb_split(float w, u16& l0, u16& l1, u16& l2) {
    u32 u0 = __float_as_uint(w);
    float h1 = __uint_as_float(u0 & 0xFFFF0000u);
    float r1 = w - h1;                       // exact
    u32 u1 = __float_as_uint(r1);
    float h2 = __uint_as_float(u1 & 0xFFFF0000u);
    float r2 = r1 - h2;                      // exact, <=8 significant bits
    u32 u2r = __float_as_uint(r2);
    l0 = (u16)(u0 >> 16); l1 = (u16)(u1 >> 16); l2 = (u16)(u2r >> 16);
}

// ------- weight prep: w1 reorder + w2 limbs + wf1 limbs ------------------------
__global__ void k_prep_w(const float* __restrict__ w1, const float* __restrict__ w2,
                         const float* __restrict__ wf1) {
    int i = blockIdx.x * blockDim.x + threadIdx.x;
    if (i < 400) {
        int oc = i & 15, kq = i >> 4;
        g_W1R[i] = w1[oc * 25 + kq];
    }
    if (i < 12800) {   // one thread -> all 3 limbs; layout [kq][l][oc][ci]
        int ci = i & 15;
        int oc = (i >> 4) & 31;
        int kq = i >> 9;
        u16 l0, l1, l2;
        limb_split(w2[oc * 400 + ci * 25 + kq], l0, l1, l2);
        int base = kq * 1536 + (oc << 4) + ci;
        g_W2L[base] = l0; g_W2L[base + 512] = l1; g_W2L[base + 1024] = l2;
    }
    if (i < 448 * 1568) {  // layout (l*448+n)*1568+k
        int n = i / 1568, k = i - n * 1568;
        float w = (n < 410) ? wf1[n * 1568 + k] : 0.f;
        u16 l0, l1, l2;
        limb_split(w, l0, l1, l2);
        g_WF1L[i] = l0;
        g_WF1L[i + 448 * 1568] = l1;
        g_WF1L[i + 2 * 448 * 1568] = l2;
    }
}

// ---- conv1 on P0: 1->16ch 28x28 5x5 pad2; spike + 2x2 pool fully in registers --
__global__ __launch_bounds__(448) void k_conv1() {
    __shared__ float in_s[32 * 33];   // rows padded to 33 floats
    __shared__ float w_s[400];        // [kq][oc]
    int tb = blockIdx.x; int t = tb >> 5, b = tb & 31;
    int tid = threadIdx.x;
    for (int i = tid; i < 1056; i += 448) in_s[i] = 0.f;
    __syncthreads();
    const float* src = &g_S0[t * (NB * 784) + b * 784];
    for (int i = tid; i < 784; i += 448) {
        int y = i / 28, x = i - y * 28;
        in_s[(y + 2) * 33 + (x + 2)] = src[i];
    }
    for (int i = tid; i < 400; i += 448) w_s[i] = g_W1R[i];
    __syncthreads();

    int oc  = tid / 28;
    int rem = tid - oc * 28;
    int py  = rem >> 1;
    int xh  = rem & 1;
    int xb  = xh * 14;

    float acc0[14], acc1[14];
    #pragma unroll
    for (int x = 0; x < 14; x++) { acc0[x] = 0.f; acc1[x] = 0.f; }

    #pragma unroll
    for (int r6 = 0; r6 < 6; r6++) {
        float rin[18];
        #pragma unroll
        for (int j = 0; j < 18; j++) rin[j] = in_s[(2 * py + r6) * 33 + xb + j];
        if (r6 <= 4) {
            #pragma unroll
            for (int kx = 0; kx < 5; kx++) {
                float w = w_s[(r6 * 5 + kx) * 16 + oc];
                #pragma unroll
                for (int x = 0; x < 14; x++) acc0[x] += w * rin[x + kx];
            }
        }
        if (r6 >= 1) {
            #pragma unroll
            for (int kx = 0; kx < 5; kx++) {
                float w = w_s[((r6 - 1) * 5 + kx) * 16 + oc];
                #pragma unroll
                for (int x = 0; x < 14; x++) acc1[x] += w * rin[x + kx];
            }
        }
    }

    float* dstp = &g_U1[(size_t)t * (NB * 3136) + b * 3136 + oc * 196 + py * 14 + xh * 7];
    #pragma unroll
    for (int xp = 0; xp < 7; xp++) {
        float s = ((acc0[2 * xp] >= 1.0f) ? 1.0f : 0.0f)
                + ((acc0[2 * xp + 1] >= 1.0f) ? 1.0f : 0.0f)
                + ((acc1[2 * xp] >= 1.0f) ? 1.0f : 0.0f)
                + ((acc1[2 * xp + 1] >= 1.0f) ? 1.0f : 0.0f);
        dstp[xp] = 1.1f * s;
    }
}

// ------- psp + spike scan -> bf16, 2 pixels per thread (float2 loads) -----------
__global__ void k_psp_spike_b2(const float* __restrict__ u, __nv_bfloat16* __restrict__ sout,
                               int plane) {
    int i = blockIdx.x * blockDim.x + threadIdx.x;
    int half = plane >> 1;
    if (i >= half) return;
    const float2* p = (const float2*)u;
    u32* q = (u32*)sout;
    float a1 = 0.f, a2 = 0.f, b1 = 0.f, b2 = 0.f;
    #pragma unroll 4
    for (int t = 0; t < T_SIM; t++) {
        float2 x = p[(size_t)t * half + i];
        a2 = R_DEC * (a2 + a1); a1 = R_DEC * a1 + x.x;
        b2 = R_DEC * (b2 + b1); b1 = R_DEC * b1 + x.y;
        u32 sa = (C_EPS * a2 >= 1.0f) ? 0x3F80u : 0u;
        u32 sb = (C_EPS * b2 >= 1.0f) ? 0x3F80u : 0u;
        q[(size_t)t * half + i] = sa | (sb << 16);
    }
}

// ------- fused: psp+spike (full res) -> 2x2 pool(x1.1) -> psp+spike ------------
template <typename TOut>
__global__ void k_fused_pp(const float* __restrict__ uin, TOut* __restrict__ sout,
                           int Hin, int planeIn, int planeOut, int total) {
    int i = blockIdx.x * blockDim.x + threadIdx.x;
    if (i >= total) return;
    int ho = Hin >> 1;
    int x  = i % ho;
    int y  = (i / ho) % ho;
    int bc = i / (ho * ho);
    const float* base = uin + bc * Hin * Hin + (2 * y) * Hin + 2 * x;

    float a1 = 0.f, a2 = 0.f, b1 = 0.f, b2 = 0.f;
    float c1 = 0.f, c2 = 0.f, d1 = 0.f, d2 = 0.f;
    float o1 = 0.f, o2 = 0.f;

    #pragma unroll 4
    for (int t = 0; t < T_SIM; t++) {
        float2 top = *(const float2*)(base + (size_t)t * planeIn);
        float2 bot = *(const float2*)(base + (size_t)t * planeIn + Hin);

        a2 = R_DEC * (a2 + a1); a1 = R_DEC * a1 + top.x;
        b2 = R_DEC * (b2 + b1); b1 = R_DEC * b1 + top.y;
        c2 = R_DEC * (c2 + c1); c1 = R_DEC * c1 + bot.x;
        d2 = R_DEC * (d2 + d1); d1 = R_DEC * d1 + bot.y;

        float spkA = (C_EPS * a2 >= 1.0f) ? 1.0f : 0.0f;
        float spkB = (C_EPS * b2 >= 1.0f) ? 1.0f : 0.0f;
        float spkC = (C_EPS * c2 >= 1.0f) ? 1.0f : 0.0f;
        float spkD = (C_EPS * d2 >= 1.0f) ? 1.0f : 0.0f;
        float pool = 1.1f * ((spkA + spkB) + (spkC + spkD));

        o2 = R_DEC * (o2 + o1); o1 = R_DEC * o1 + pool;
        sout[(size_t)t * planeOut + i] = (TOut)((C_EPS * o2 >= 1.0f) ? 1.0f : 0.0f);
    }
}

// ---------------- generic psp + spike (in place, fp32) -------------------------
__global__ void k_psp(float* __restrict__ u, int plane) {
    int i = blockIdx.x * blockDim.x + threadIdx.x;
    if (i >= plane) return;
    float* p = u + i;
    float s1 = 0.f, s2 = 0.f;
    #pragma unroll 4
    for (int t = 0; t < T_SIM; t++) {
        float x = p[(size_t)t * plane];
        s2 = R_DEC * (s2 + s1);
        s1 = R_DEC * s1 + x;
        p[(size_t)t * plane] = (C_EPS * s2 >= 1.0f) ? 1.0f : 0.0f;
    }
}

// ---- mma.m16n8k16 bf16 helper ---------------------------------------------------
__device__ __forceinline__ void mma16816(float* c, const u32* a, u32 b0, u32 b1) {
    asm volatile(
        "mma.sync.aligned.m16n8k16.row.col.f32.bf16.bf16.f32 "
        "{%0,%1,%2,%3}, {%4,%5,%6,%7}, {%8,%9}, {%0,%1,%2,%3};"
        : "+f"(c[0]), "+f"(c[1]), "+f"(c[2]), "+f"(c[3])
        : "r"(a[0]), "r"(a[1]), "r"(a[2]), "r"(a[3]), "r"(b0), "r"(b1));
}

// ---- conv2 via tensor cores: 2 time-planes per block, interleaved-ci smem -------
// smem pixel layout (bf16 idx within pixel): ci<8 -> (ci>>1)*4 + (ci&1)
//                                            ci>=8 -> ((ci-8)>>1)*4 + 2 + (ci&1)
// so u64 slot tq of a pixel = {b0 = ci(2tq,2tq+1), b1 = ci(2tq+8,2tq+9)} -> one
// conflict-free LDS.64 replaces two 4-way-conflicted LDS.32.
__global__ __launch_bounds__(256) void k_conv2_mma() {
    __shared__ __nv_bfloat16 in_s[2][18 * 24 * 16];   // 27648 B
    int tb = blockIdx.x; int tp = tb >> 5, b = tb & 31;
    int t0 = tp * 2;
    int tid = threadIdx.x, warp = tid >> 5, lane = tid & 31;

    u32* z = (u32*)in_s;
    for (int i = tid; i < 6912; i += 256) z[i] = 0u;
    __syncthreads();
    #pragma unroll
    for (int pl = 0; pl < 2; pl++) {
        const __nv_bfloat16* src = g_S1p + (size_t)(t0 + pl) * (NB * 3136) + b * 3136;
        for (int i = tid; i < 3136; i += 256) {
            int ci = i / 196, p = i - ci * 196;
            int y = p / 14, x = p - y * 14;
            int bidx = (ci < 8) ? ((ci >> 1) * 4 + (ci & 1))
                                : (((ci - 8) >> 1) * 4 + 2 + (ci & 1));
            in_s[pl][((y + 2) * 24 + (x + 2)) * 16 + bidx] = src[i];
        }
    }
    __syncthreads();

    int g  = lane >> 2;
    int tq = lane & 3;
    int m  = warp >> 2;
    int nr0 = (warp & 3) * 7;

    float acc[2][7][4];
    #pragma unroll
    for (int pl = 0; pl < 2; pl++)
        #pragma unroll
        for (int j = 0; j < 7; j++)
            #pragma unroll
            for (int q = 0; q < 4; q++) acc[pl][j][q] = 0.f;

    const u32* wl = (const u32*)g_W2L;
    const u64* bsm0 = (const u64*)in_s[0];
    const u64* bsm1 = (const u64*)in_s[1];

    #pragma unroll 1
    for (int kq = 0; kq < 25; kq++) {
        int ky = kq / 5, kx = kq - ky * 5;
        u32 af[3][4];
        #pragma unroll
        for (int l = 0; l < 3; l++) {
            int base = ((kq * 3 + l) * 32 + m * 16 + g) * 8;
            af[l][0] = __ldg(&wl[base + tq]);
            af[l][1] = __ldg(&wl[base + 64 + tq]);
            af[l][2] = __ldg(&wl[base + tq + 4]);
            af[l][3] = __ldg(&wl[base + 64 + tq + 4]);
        }
        #pragma unroll
        for (int j = 0; j < 7; j++) {
            int nr = nr0 + j;
            int y = nr >> 1, xh = (nr & 1) * 8;
            int pix = (y + ky) * 24 + (xh + g + kx);
            u64 v0 = bsm0[pix * 4 + tq];
            u64 v1 = bsm1[pix * 4 + tq];
            u32 b00 = (u32)v0, b01 = (u32)(v0 >> 32);
            u32 b10 = (u32)v1, b11 = (u32)(v1 >> 32);
            mma16816(acc[0][j], af[0], b00, b01);
            mma16816(acc[0][j], af[1], b00, b01);
            mma16816(acc[0][j], af[2], b00, b01);
            mma16816(acc[1][j], af[0], b10, b11);
            mma16816(acc[1][j], af[1], b10, b11);
            mma16816(acc[1][j], af[2], b10, b11);
        }
    }

    int oc0 = m * 16 + g;
    int xp0 = tq * 2;
    #pragma unroll
    for (int pl = 0; pl < 2; pl++) {
        float* dst = g_U2 + (size_t)(t0 + pl) * (NB * 6272) + b * 6272;
        #pragma unroll
        for (int j = 0; j < 7; j++) {
            int nr = nr0 + j;
            int y = nr >> 1, xh = (nr & 1) * 8;
            int xp = xh + xp0;
            if (xp <= 12) {
                float2 v0; v0.x = acc[pl][j][0]; v0.y = acc[pl][j][1];
                float2 v1; v1.x = acc[pl][j][2]; v1.y = acc[pl][j][3];
                *(float2*)&dst[oc0 * 196 + y * 14 + xp] = v0;
                *(float2*)&dst[(oc0 + 8) * 196 + y * 14 + xp] = v1;
            }
        }
    }
}

// ---- fc1 via tensor cores: C[3200x410] = S2p(bf16 spikes) x wf1^T (3 limbs) ----
__global__ __launch_bounds__(256) void k_dense1_mma() {
    __shared__ __nv_bfloat16 As[64 * 40];        // row pad 40 bf16 (20 u32)
    __shared__ __nv_bfloat16 Bs[3 * 64 * 40];
    int m0 = blockIdx.y * 64, n0 = blockIdx.x * 64;
    int tid = threadIdx.x, warp = tid >> 5, lane = tid & 31;
    int g = lane >> 2, tq = lane & 3;
    int wm = warp >> 2, wn = warp & 3;
    u32* as32 = (u32*)As;
    u32* bs32 = (u32*)Bs;
    const u32* a_src = (const u32*)g_S2p;        // row stride 784 u32
    const u32* b_src = (const u32*)g_WF1L;       // row stride 784 u32

    float acc[2][2][4];
    #pragma unroll
    for (int mt = 0; mt < 2; mt++)
        #pragma unroll
        for (int nt = 0; nt < 2; nt++)
            #pragma unroll
            for (int q = 0; q < 4; q++) acc[mt][nt][q] = 0.f;

    int arow = tid >> 2, ac = (tid & 3) * 4;     // 64 rows x 4 u32 each

    for (int kc = 0; kc < 784; kc += 16) {       // 16 u32 = 32 bf16 per chunk
        uint4 av = *(const uint4*)&a_src[(size_t)(m0 + arow) * 784 + kc + ac];
        *(uint4*)&as32[arow * 20 + ac] = av;
        #pragma unroll
        for (int l = 0; l < 3; l++) {
            uint4 bv = *(const uint4*)&b_src[(size_t)(l * 448 + n0 + arow) * 784 + kc + ac];
            *(uint4*)&bs32[(l * 64 + arow) * 20 + ac] = bv;
        }
        __syncthreads();
        #pragma unroll
        for (int ks = 0; ks < 2; ks++) {
            int ko = ks * 8;
            u32 a[2][4];
            #pragma unroll
            for (int mt = 0; mt < 2; mt++) {
                int r = wm * 32 + mt * 16 + g;
                a[mt][0] = as32[r * 20 + ko + tq];
                a[mt][1] = as32[(r + 8) * 20 + ko + tq];
                a[mt][2] = as32[r * 20 + ko + tq + 4];
                a[mt][3] = as32[(r + 8) * 20 + ko + tq + 4];
            }
            #pragma unroll
            for (int l = 0; l < 3; l++)
                #pragma unroll
                for (int nt = 0; nt < 2; nt++) {
                    int ccol = l * 64 + wn * 16 + nt * 8 + g;
                    u32 b0 = bs32[ccol * 20 + ko + tq];
                    u32 b1 = bs32[ccol * 20 + ko + tq + 4];
                    mma16816(acc[0][nt], a[0], b0, b1);
                    mma16816(acc[1][nt], a[1], b0, b1);
                }
        }
        __syncthreads();
    }

    #pragma unroll
    for (int mt = 0; mt < 2; mt++)
        #pragma unroll
        for (int nt = 0; nt < 2; nt++) {
            int mrow = m0 + wm * 32 + mt * 16 + g;
            int n = n0 + wn * 16 + nt * 8 + tq * 2;
            if (n < 410) {
                g_U3[mrow * 410 + n] = acc[mt][nt][0];
                g_U3[(mrow + 8) * 410 + n] = acc[mt][nt][2];
            }
            if (n + 1 < 410) {
                g_U3[mrow * 410 + n + 1] = acc[mt][nt][1];
                g_U3[(mrow + 8) * 410 + n + 1] = acc[mt][nt][3];
            }
        }
}

// ---------------- fc2: [3200,10] = S3[3200,410] * wf2^T ------------------------
__global__ void k_dense2(const float* __restrict__ wf2) {
    int i = blockIdx.x * blockDim.x + threadIdx.x;
    if (i >= 32000) return;
    int m = i / 10, o = i - (i / 10) * 10;
    const float* a = &g_U3[m * 410];
    const float* w = &wf2[o * 410];
    float acc = 0.f;
    #pragma unroll 2
    for (int k = 0; k < 410; k++) acc += a[k] * w[k];
    g_U4[m * 10 + o] = acc;
}

// ---------------- final psp + spike + transpose to [b][o][t] -------------------
__global__ void k_final(float* __restrict__ out) {
    int i = threadIdx.x;                   // 320 = b*10+o
    if (i >= 320) return;
    float s1 = 0.f, s2 = 0.f;
    #pragma unroll 4
    for (int t = 0; t < T_SIM; t++) {
        float x = g_U4[t * 320 + i];
        s2 = R_DEC * (s2 + s1);
        s1 = R_DEC * s1 + x;
        out[i * T_SIM + t] = (C_EPS * s2 >= 1.0f) ? 1.0f : 0.0f;
    }
}

// -------------------------------------------------------------------------------
extern "C" void kernel_launch(void* const* d_in, const int* in_sizes, int n_in,
                              void* d_out, int out_size) {
    const float* img    = (const float*)d_in[0];
    const float* rand_u = (const float*)d_in[1];
    const float* w1     = (const float*)d_in[2];
    const float* w2     = (const float*)d_in[3];
    const float* wf1    = (const float*)d_in[4];
    const float* wf2    = (const float*)d_in[5];
    float* out = (float*)d_out;

    void *pU1, *pU2, *pU3, *pS1p, *pS2p;
    cudaGetSymbolAddress(&pU1,  g_U1);
    cudaGetSymbolAddress(&pU2,  g_U2);
    cudaGetSymbolAddress(&pU3,  g_U3);
    cudaGetSymbolAddress(&pS1p, g_S1p);
    cudaGetSymbolAddress(&pS2p, g_S2p);

    k_encode_psp<<<784, 256>>>(rand_u, img);     // encode + psp scan fused
    k_prep_w<<<2744, 256>>>(w1, w2, wf1);

    // layer 1: conv1 with spike+pool in registers, then psp+spike -> bf16
    k_conv1<<<3200, 448>>>();
    k_psp_spike_b2<<<196, 256>>>((const float*)pU1, (__nv_bfloat16*)pS1p, NB * 16 * 196);

    // layer 2: tensor-core conv (2 planes/block), then fused psp/pool chain -> bf16
    k_conv2_mma<<<1600, 256>>>();
    k_fused_pp<__nv_bfloat16><<<196, 256>>>((const float*)pU2, (__nv_bfloat16*)pS2p,
                             14, NB * 32 * 196, NB * 1568, NB * 1568);

    // fc1 on tensor cores (exact 3-limb), then scan
    dim3 g1(7, 50);
    k_dense1_mma<<<g1, 256>>>();
    k_psp<<<52, 256>>>((float*)pU3, NB * 410);

    k_dense2<<<125, 256>>>(wf2);
    k_final<<<1, 320>>>(out);
}